// round 11
// baseline (speedup 1.0000x reference)
#include <cuda_runtime.h>
#include <cuda_bf16.h>
#include <math.h>
#include <stdint.h>

#define NN   51200
#define GG   256
#define NPG  200
#define EE   409600
#define EPG  1600
#define CH   128
#define NE   (EPG + NPG)   // edges per graph incl self-loops = 1800

// ---------------- scratch (device globals; no allocs allowed) ----------------
__device__ float g_h1[(size_t)NN * 512];
__device__ float g_h2[(size_t)2 * NN * CH];         // split-K partials (2x)
__device__ __nv_bfloat16 g_xh[(size_t)NN * 768];
__device__ __nv_bfloat16 g_xl[(size_t)NN * 768];
__device__ __nv_bfloat16 g_o1h[(size_t)NN * 512];
__device__ __nv_bfloat16 g_o1l[(size_t)NN * 512];
__device__ __nv_bfloat16 g_w1h[512 * 768];
__device__ __nv_bfloat16 g_w1l[512 * 768];
__device__ __nv_bfloat16 g_w2h[128 * 512];
__device__ __nv_bfloat16 g_w2l[128 * 512];
__device__ unsigned short g_csr[(size_t)GG * NE];
__device__ int g_csro[GG * (NPG + 1)];

#define SWZB(o) ((o) ^ (((o) >> 3) & 0x70))

// =============== fused prep: x split + W1/W2 split + CSR + loss init ===============
__global__ void prep(const float* __restrict__ x, __nv_bfloat16* __restrict__ xh,
                     __nv_bfloat16* __restrict__ xl,
                     const float* __restrict__ W1, const float* __restrict__ W2,
                     const int* __restrict__ es, const int* __restrict__ ed,
                     float* __restrict__ loss) {
    const int b = blockIdx.x, tid = threadIdx.x;
    if (b < 4096) {
        const size_t n4 = (size_t)NN * 768 / 4;
        size_t i = (size_t)b * 256 + tid;
        const size_t stride = 4096 * 256;
        for (; i < n4; i += stride) {
            float4 v = ((const float4*)x)[i];
            __nv_bfloat16 h0 = __float2bfloat16(v.x), h1 = __float2bfloat16(v.y);
            __nv_bfloat16 h2 = __float2bfloat16(v.z), h3 = __float2bfloat16(v.w);
            __nv_bfloat16 l0 = __float2bfloat16(v.x - __bfloat162float(h0));
            __nv_bfloat16 l1 = __float2bfloat16(v.y - __bfloat162float(h1));
            __nv_bfloat16 l2 = __float2bfloat16(v.z - __bfloat162float(h2));
            __nv_bfloat16 l3 = __float2bfloat16(v.w - __bfloat162float(h3));
            ((__nv_bfloat162*)xh)[2 * i]     = __halves2bfloat162(h0, h1);
            ((__nv_bfloat162*)xh)[2 * i + 1] = __halves2bfloat162(h2, h3);
            ((__nv_bfloat162*)xl)[2 * i]     = __halves2bfloat162(l0, l1);
            ((__nv_bfloat162*)xl)[2 * i + 1] = __halves2bfloat162(l2, l3);
        }
    } else if (b < 5888) {
        const bool w1 = (b < 5632);
        const int K = w1 ? 768 : 512, Nn = w1 ? 512 : 128;
        const float* W = w1 ? W1 : W2;
        __nv_bfloat16* hi = w1 ? g_w1h : g_w2h;
        __nv_bfloat16* lo = w1 ? g_w1l : g_w2l;
        int idx = (b - (w1 ? 4096 : 5632)) * 256 + tid;
        if (idx < Nn * K) {
            int n = idx / K, k = idx - n * K;
            float v = W[(size_t)k * Nn + n];
            __nv_bfloat16 h = __float2bfloat16(v);
            hi[idx] = h;
            lo[idx] = __float2bfloat16(v - __bfloat162float(h));
        }
    } else {
        const int g = b - 5888;
        if (g == 0 && tid == 0) *loss = 0.f;
        __shared__ int cnt[NPG + 1];
        __shared__ int cur[NPG];
        __shared__ unsigned short sd[NE];
        for (int i = tid; i <= NPG; i += blockDim.x) cnt[i] = 0;
        __syncthreads();
        for (int e = tid; e < NE; e += blockDim.x) {
            int d = (e < EPG) ? (ed[g * EPG + e] - g * NPG) : (e - EPG);
            sd[e] = (unsigned short)d;
            atomicAdd(&cnt[d], 1);
        }
        __syncthreads();
        if (tid == 0) {
            int run = 0;
            for (int i = 0; i < NPG; i++) {
                int c = cnt[i]; cnt[i] = run;
                g_csro[g * (NPG + 1) + i] = run;
                run += c;
            }
            g_csro[g * (NPG + 1) + NPG] = run;
        }
        __syncthreads();
        for (int i = tid; i < NPG; i += blockDim.x) cur[i] = cnt[i];
        __syncthreads();
        for (int e = tid; e < NE; e += blockDim.x) {
            int s = (e < EPG) ? (es[g * EPG + e] - g * NPG) : (e - EPG);
            int p = atomicAdd(&cur[sd[e]], 1);
            g_csr[(size_t)g * NE + p] = (unsigned short)s;
        }
    }
}

// ============================ HMMA split-bf16 GEMM ============================
__device__ __forceinline__ void ldsm4(uint32_t addr, uint32_t& r0, uint32_t& r1,
                                      uint32_t& r2, uint32_t& r3) {
    asm volatile("ldmatrix.sync.aligned.m8n8.x4.shared.b16 {%0,%1,%2,%3}, [%4];"
                 : "=r"(r0), "=r"(r1), "=r"(r2), "=r"(r3) : "r"(addr));
}

// C[M x Nn] (+z partial) = A[M, zoff:zoff+kd] * B[Nn, zoff:zoff+kd]^T, split-bf16 3-pass.
// ldk = row stride of A/B; kd = K depth per z-slice; czstride = C offset per blockIdx.z.
__global__ void __launch_bounds__(256, 2)
gemm_hmma(const __nv_bfloat16* __restrict__ Ahi, const __nv_bfloat16* __restrict__ Alo,
          const __nv_bfloat16* __restrict__ Bhi, const __nv_bfloat16* __restrict__ Blo,
          float* __restrict__ C, int Nn, int ldk, int kd, size_t czstride) {
    constexpr int TILE = 128 * 128;
    constexpr int STG  = 2 * TILE;
    extern __shared__ char smb[];
    uint32_t sb;
    asm("{ .reg .u64 tt; cvta.to.shared.u64 tt, %1; cvt.u32.u64 %0, tt; }"
        : "=r"(sb) : "l"(smb));
    const int tid = threadIdx.x, lane = tid & 31, wid = tid >> 5;
    const int g = lane >> 2, t = lane & 3;
    const int bm = blockIdx.y * 128, bn = blockIdx.x * 128;
    const int zoff = blockIdx.z * kd;
    C += (size_t)blockIdx.z * czstride;
    const int wm = (wid >> 1) * 32, wn = (wid & 1) * 64;
    const int nk = kd >> 6, nch = 3 * nk;
    const int aoff = ((lane & 7) + ((lane >> 3) & 1) * 8) * 128 + (lane >> 4) * 16;
    const int boff = ((lane & 7) + ((lane >> 4) & 1) * 8) * 128 + ((lane >> 3) & 1) * 16;

    float acc[2][8][4];
#pragma unroll
    for (int mf = 0; mf < 2; mf++)
#pragma unroll
        for (int nf = 0; nf < 8; nf++)
#pragma unroll
            for (int j = 0; j < 4; j++) acc[mf][nf][j] = 0.f;

    auto prefetch = [&](int c) {
        int pass = (c >= 2 * nk) ? 2 : ((c >= nk) ? 1 : 0);
        int kk = zoff + ((c - pass * nk) << 6);
        const __nv_bfloat16* As = (pass < 2) ? Ahi : Alo;
        const __nv_bfloat16* Bs = (pass == 1) ? Blo : Bhi;
        uint32_t st = sb + (c % 3) * STG;
        const __nv_bfloat16* Ag = As + (size_t)bm * ldk + kk;
        const __nv_bfloat16* Bg = Bs + (size_t)bn * ldk + kk;
#pragma unroll
        for (int u = 0; u < 4; u++) {
            int v = u * 256 + tid;
            int r = v >> 3, c16 = v & 7;
            asm volatile("cp.async.cg.shared.global [%0], [%1], 16;"
                         :: "r"(st + SWZB(r * 128 + c16 * 16)),
                            "l"(Ag + (size_t)r * ldk + c16 * 8) : "memory");
        }
#pragma unroll
        for (int u = 0; u < 4; u++) {
            int v = u * 256 + tid;
            int r = v >> 3, c16 = v & 7;
            asm volatile("cp.async.cg.shared.global [%0], [%1], 16;"
                         :: "r"(st + TILE + SWZB(r * 128 + c16 * 16)),
                            "l"(Bg + (size_t)r * ldk + c16 * 8) : "memory");
        }
        asm volatile("cp.async.commit_group;" ::: "memory");
    };

    prefetch(0);
    prefetch(1);
    for (int c = 0; c < nch; c++) {
        if (c == nch - 1)
            asm volatile("cp.async.wait_group 0;" ::: "memory");
        else
            asm volatile("cp.async.wait_group 1;" ::: "memory");
        __syncthreads();
        if (c + 2 < nch) prefetch(c + 2);
        const uint32_t ab = sb + (c % 3) * STG;
        const uint32_t bb = ab + TILE;
#pragma unroll
        for (int ks = 0; ks < 4; ks++) {
            uint32_t af[2][4], bf[8][2];
#pragma unroll
            for (int mf = 0; mf < 2; mf++)
                ldsm4(ab + SWZB((wm + mf * 16) * 128 + ks * 32 + aoff),
                      af[mf][0], af[mf][1], af[mf][2], af[mf][3]);
#pragma unroll
            for (int nf2 = 0; nf2 < 4; nf2++)
                ldsm4(bb + SWZB((wn + nf2 * 16) * 128 + ks * 32 + boff),
                      bf[2 * nf2][0], bf[2 * nf2][1], bf[2 * nf2 + 1][0], bf[2 * nf2 + 1][1]);
#pragma unroll
            for (int mf = 0; mf < 2; mf++)
#pragma unroll
                for (int nf = 0; nf < 8; nf++) {
                    asm volatile(
                        "mma.sync.aligned.m16n8k16.row.col.f32.bf16.bf16.f32 "
                        "{%0,%1,%2,%3}, {%4,%5,%6,%7}, {%8,%9}, {%0,%1,%2,%3};"
                        : "+f"(acc[mf][nf][0]), "+f"(acc[mf][nf][1]),
                          "+f"(acc[mf][nf][2]), "+f"(acc[mf][nf][3])
                        : "r"(af[mf][0]), "r"(af[mf][1]), "r"(af[mf][2]), "r"(af[mf][3]),
                          "r"(bf[nf][0]), "r"(bf[nf][1]));
                }
        }
    }

#pragma unroll
    for (int mf = 0; mf < 2; mf++)
#pragma unroll
        for (int nf = 0; nf < 8; nf++) {
            int row = bm + wm + mf * 16 + g;
            int col = bn + wn + nf * 8 + t * 2;
            *(float2*)&C[(size_t)row * Nn + col] =
                make_float2(acc[mf][nf][0], acc[mf][nf][1]);
            *(float2*)&C[(size_t)(row + 8) * Nn + col] =
                make_float2(acc[mf][nf][2], acc[mf][nf][3]);
        }
}

// ====== layer-1 GAT: dots + softmax + aggregate -> bf16 hi/lo, block per (graph, head) ======
__global__ void gat_agg1(const float* __restrict__ h, const float* __restrict__ a_s,
                         const float* __restrict__ a_d, const float* __restrict__ bias,
                         __nv_bfloat16* __restrict__ outh, __nv_bfloat16* __restrict__ outl) {
    extern __shared__ float smem[];
    float* hb  = smem;                       // NPG*CH
    float* asr = hb + NPG * CH;
    float* adr = asr + NPG;
    int* soff  = (int*)(adr + NPG);
    unsigned short* ssrc = (unsigned short*)(soff + NPG + 1);

    const int g = blockIdx.x, hd = blockIdx.y;
    const int tid = threadIdx.x, wid = tid >> 5, lane = tid & 31;
    const int base = g * NPG;

    for (int i = tid; i < NPG * (CH / 4); i += blockDim.x) {
        int r = i / (CH / 4), c4 = (i % (CH / 4)) * 4;
        *(float4*)&hb[r * CH + c4] =
            *(const float4*)(h + (size_t)(base + r) * 512 + hd * CH + c4);
    }
    for (int i = tid; i <= NPG; i += blockDim.x) soff[i] = g_csro[g * (NPG + 1) + i];
    for (int i = tid; i < NE / 2; i += blockDim.x)
        ((uint32_t*)ssrc)[i] = ((const uint32_t*)(g_csr + (size_t)g * NE))[i];
    __syncthreads();

    {
        float4 s4 = *(const float4*)(a_s + hd * CH + lane * 4);
        float4 d4 = *(const float4*)(a_d + hd * CH + lane * 4);
        for (int r = wid; r < NPG; r += 8) {
            float4 v = *(float4*)&hb[r * CH + lane * 4];
            float ps = v.x * s4.x + v.y * s4.y + v.z * s4.z + v.w * s4.w;
            float pd = v.x * d4.x + v.y * d4.y + v.z * d4.z + v.w * d4.w;
#pragma unroll
            for (int o = 16; o; o >>= 1) {
                ps += __shfl_xor_sync(0xffffffffu, ps, o);
                pd += __shfl_xor_sync(0xffffffffu, pd, o);
            }
            if (lane == 0) { asr[r] = ps; adr[r] = pd; }
        }
    }
    __syncthreads();

    for (int d = wid; d < NPG; d += 8) {
        const int j0 = soff[d], j1 = soff[d + 1];
        const float add = adr[d];
        float m = -1e30f;
        for (int j = j0; j < j1; j++) {
            float l = asr[ssrc[j]] + add;
            l = l > 0.f ? l : 0.2f * l;
            m = fmaxf(m, l);
        }
        float sum = 0.f;
        float4 acc = make_float4(0.f, 0.f, 0.f, 0.f);
        for (int j = j0; j < j1; j++) {
            int s = ssrc[j];
            float l = asr[s] + add;
            l = l > 0.f ? l : 0.2f * l;
            float e = expf(l - m);
            sum += e;
            float4 hv = *(float4*)&hb[s * CH + lane * 4];
            acc.x += e * hv.x; acc.y += e * hv.y;
            acc.z += e * hv.z; acc.w += e * hv.w;
        }
        float inv = 1.f / (sum + 1e-16f);
        float4 b4 = *(const float4*)(bias + hd * CH + lane * 4);
        acc.x = fmaxf(acc.x * inv + b4.x, 0.f);
        acc.y = fmaxf(acc.y * inv + b4.y, 0.f);
        acc.z = fmaxf(acc.z * inv + b4.z, 0.f);
        acc.w = fmaxf(acc.w * inv + b4.w, 0.f);
        size_t o = (size_t)(base + d) * 512 + hd * CH + lane * 4;
        __nv_bfloat16 h0 = __float2bfloat16(acc.x), h1 = __float2bfloat16(acc.y);
        __nv_bfloat16 h2 = __float2bfloat16(acc.z), h3 = __float2bfloat16(acc.w);
        *(__nv_bfloat162*)(outh + o)     = __halves2bfloat162(h0, h1);
        *(__nv_bfloat162*)(outh + o + 2) = __halves2bfloat162(h2, h3);
        __nv_bfloat16 l0 = __float2bfloat16(acc.x - __bfloat162float(h0));
        __nv_bfloat16 l1 = __float2bfloat16(acc.y - __bfloat162float(h1));
        __nv_bfloat16 l2 = __float2bfloat16(acc.z - __bfloat162float(h2));
        __nv_bfloat16 l3 = __float2bfloat16(acc.w - __bfloat162float(h3));
        *(__nv_bfloat162*)(outl + o)     = __halves2bfloat162(l0, l1);
        *(__nv_bfloat162*)(outl + o + 2) = __halves2bfloat162(l2, l3);
    }
}

// ====== fused layer-2 GAT + cluster softmax + aggregate loss + readout MLP ======
// One block per graph. h2 = p0 + p1 (split-K partials) summed during staging.
__global__ void gat2_head(const float* __restrict__ h2a, const float* __restrict__ h2b,
                          const float* __restrict__ a_s, const float* __restrict__ a_d,
                          const float* __restrict__ bias,
                          const float* __restrict__ Wc, const float* __restrict__ bc,
                          const int* __restrict__ es, const int* __restrict__ ed,
                          const float* __restrict__ Wf1, const float* __restrict__ bf1,
                          const float* __restrict__ Wf2, const float* __restrict__ bf2,
                          float* __restrict__ out, float* __restrict__ loss) {
    extern __shared__ float smem[];
    float* hb  = smem;                        // NPG*CH
    float* asr = hb + NPG * CH;               // NPG
    float* adr = asr + NPG;                   // NPG
    float* s0a = adr + NPG;                   // NPG
    float* s1a = s0a + NPG;                   // NPG
    float* sub = s1a + NPG;                   // CH
    float* hid = sub + CH;                    // CH
    float* sa  = hid + CH;                    // 4
    int* soff  = (int*)(sa + 4);              // NPG+1
    unsigned short* ssrc = (unsigned short*)(soff + NPG + 1);  // NE

    const int g = blockIdx.x;
    const int tid = threadIdx.x, wid = tid >> 5, lane = tid & 31;
    const int base = g * NPG;

    for (int i = tid; i < NPG * (CH / 4); i += blockDim.x) {
        int r = i / (CH / 4), c4 = (i % (CH / 4)) * 4;
        size_t off = (size_t)(base + r) * CH + c4;
        float4 va = *(const float4*)(h2a + off);
        float4 vb = *(const float4*)(h2b + off);
        *(float4*)&hb[r * CH + c4] =
            make_float4(va.x + vb.x, va.y + vb.y, va.z + vb.z, va.w + vb.w);
    }
    for (int i = tid; i <= NPG; i += blockDim.x) soff[i] = g_csro[g * (NPG + 1) + i];
    for (int i = tid; i < NE / 2; i += blockDim.x)
        ((uint32_t*)ssrc)[i] = ((const uint32_t*)(g_csr + (size_t)g * NE))[i];
    if (tid < CH) sub[tid] = 0.f;
    if (tid < 4) sa[tid] = 0.f;
    __syncthreads();

    {
        float4 s4 = *(const float4*)(a_s + lane * 4);
        float4 d4 = *(const float4*)(a_d + lane * 4);
        for (int r = wid; r < NPG; r += 8) {
            float4 v = *(float4*)&hb[r * CH + lane * 4];
            float ps = v.x * s4.x + v.y * s4.y + v.z * s4.z + v.w * s4.w;
            float pd = v.x * d4.x + v.y * d4.y + v.z * d4.z + v.w * d4.w;
#pragma unroll
            for (int o = 16; o; o >>= 1) {
                ps += __shfl_xor_sync(0xffffffffu, ps, o);
                pd += __shfl_xor_sync(0xffffffffu, pd, o);
            }
            if (lane == 0) { asr[r] = ps; adr[r] = pd; }
        }
    }
    __syncthreads();

    float2 w01[4];
#pragma unroll
    for (int j = 0; j < 4; j++)
        w01[j] = *(const float2*)(Wc + (lane * 4 + j) * 2);
    const float bc0 = bc[0], bc1 = bc[1];
    const float4 b4 = *(const float4*)(bias + lane * 4);

    for (int d = wid; d < NPG; d += 8) {
        const int j0 = soff[d], j1 = soff[d + 1];
        const float add = adr[d];
        float m = -1e30f;
        for (int j = j0; j < j1; j++) {
            float l = asr[ssrc[j]] + add;
            l = l > 0.f ? l : 0.2f * l;
            m = fmaxf(m, l);
        }
        float sum = 0.f;
        float4 acc = make_float4(0.f, 0.f, 0.f, 0.f);
        for (int j = j0; j < j1; j++) {
            int s = ssrc[j];
            float l = asr[s] + add;
            l = l > 0.f ? l : 0.2f * l;
            float e = expf(l - m);
            sum += e;
            float4 hv = *(float4*)&hb[s * CH + lane * 4];
            acc.x += e * hv.x; acc.y += e * hv.y;
            acc.z += e * hv.z; acc.w += e * hv.w;
        }
        float inv = 1.f / (sum + 1e-16f);
        acc.x = fmaxf(acc.x * inv + b4.x, 0.f);
        acc.y = fmaxf(acc.y * inv + b4.y, 0.f);
        acc.z = fmaxf(acc.z * inv + b4.z, 0.f);
        acc.w = fmaxf(acc.w * inv + b4.w, 0.f);
        // cluster softmax S = softmax(o2 @ Wc + bc)  (xor-reduce -> all lanes)
        float p0 = acc.x * w01[0].x + acc.y * w01[1].x + acc.z * w01[2].x + acc.w * w01[3].x;
        float p1 = acc.x * w01[0].y + acc.y * w01[1].y + acc.z * w01[2].y + acc.w * w01[3].y;
#pragma unroll
        for (int o = 16; o; o >>= 1) {
            p0 += __shfl_xor_sync(0xffffffffu, p0, o);
            p1 += __shfl_xor_sync(0xffffffffu, p1, o);
        }
        float z0 = p0 + bc0, z1 = p1 + bc1;
        float mm = fmaxf(z0, z1);
        float e0 = expf(z0 - mm), e1 = expf(z1 - mm);
        float is = 1.f / (e0 + e1);
        float s0v = e0 * is, s1v = e1 * is;
        if (lane == 0) { s0a[d] = s0v; s1a[d] = s1v; }
        // sub[c] += S0[d] * o2[d][c]  (spread-bank smem atomics)
        atomicAdd(&sub[lane * 4 + 0], s0v * acc.x);
        atomicAdd(&sub[lane * 4 + 1], s0v * acc.y);
        atomicAdd(&sub[lane * 4 + 2], s0v * acc.z);
        atomicAdd(&sub[lane * 4 + 3], s0v * acc.w);
    }
    __syncthreads();

    // aggregate loss over original edges (S from smem)
    {
        float a00 = 0.f, a01 = 0.f, a10 = 0.f, a11 = 0.f;
        for (int e = tid; e < EPG; e += blockDim.x) {
            int so = es[g * EPG + e] - base, dn = ed[g * EPG + e] - base;
            float ss0 = s0a[so], ss1 = s1a[so];
            float d0 = s0a[dn], d1 = s1a[dn];
            a00 += ss0 * d0; a01 += ss0 * d1; a10 += ss1 * d0; a11 += ss1 * d1;
        }
#pragma unroll
        for (int o = 16; o; o >>= 1) {
            a00 += __shfl_xor_sync(0xffffffffu, a00, o);
            a01 += __shfl_xor_sync(0xffffffffu, a01, o);
            a10 += __shfl_xor_sync(0xffffffffu, a10, o);
            a11 += __shfl_xor_sync(0xffffffffu, a11, o);
        }
        if (lane == 0) {
            atomicAdd(&sa[0], a00); atomicAdd(&sa[1], a01);
            atomicAdd(&sa[2], a10); atomicAdd(&sa[3], a11);
        }
    }
    __syncthreads();
    if (tid == 0) {
        float r0 = fmaxf(fabsf(sa[0]) + fabsf(sa[1]), 1e-5f);
        float r1 = fmaxf(fabsf(sa[2]) + fabsf(sa[3]), 1e-5f);
        float d0 = sa[0] / r0 - 1.f, d1 = sa[3] / r1 - 1.f;
        float lg = 0.5f * (d0 * d0 + d1 * d1);
        atomicAdd(loss, lg * (1.f / (float)GG));
    }

    // readout MLP: relu(sub @ Wf1 + bf1) @ Wf2 + bf2
    if (tid < CH) {
        float hh = bf1[tid];
        for (int c = 0; c < CH; c++) hh += sub[c] * Wf1[c * CH + tid];
        hid[tid] = fmaxf(hh, 0.f);
    }
    __syncthreads();
    int w = tid >> 5;
    if (w < 2) {
        float p = 0.f;
        for (int j = lane; j < CH; j += 32) p += hid[j] * Wf2[j * 2 + w];
#pragma unroll
        for (int o = 16; o; o >>= 1) p += __shfl_down_sync(0xffffffffu, p, o);
        if (lane == 0) out[g * 2 + w] = p + bf2[w];
    }
}

// ============================ launcher ============================
extern "C" void kernel_launch(void* const* d_in, const int* in_sizes, int n_in,
                              void* d_out, int out_size) {
    const float* x   = (const float*)d_in[0];
    const int*   ei  = (const int*)d_in[1];
    const float* W1  = (const float*)d_in[3];
    const float* as1 = (const float*)d_in[4];
    const float* ad1 = (const float*)d_in[5];
    const float* b1  = (const float*)d_in[6];
    const float* W2  = (const float*)d_in[7];
    const float* as2 = (const float*)d_in[8];
    const float* ad2 = (const float*)d_in[9];
    const float* b2  = (const float*)d_in[10];
    const float* Wc  = (const float*)d_in[11];
    const float* bc  = (const float*)d_in[12];
    const float* Wf1 = (const float*)d_in[13];
    const float* bf1 = (const float*)d_in[14];
    const float* Wf2 = (const float*)d_in[15];
    const float* bf2 = (const float*)d_in[16];
    const int* es = ei;
    const int* ed = ei + EE;
    float* out = (float*)d_out;

    float *h1, *h2;
    __nv_bfloat16 *xh, *xl, *o1h, *o1l, *w1h, *w1l, *w2h, *w2l;
    cudaGetSymbolAddress((void**)&h1, g_h1);
    cudaGetSymbolAddress((void**)&h2, g_h2);
    cudaGetSymbolAddress((void**)&xh, g_xh);
    cudaGetSymbolAddress((void**)&xl, g_xl);
    cudaGetSymbolAddress((void**)&o1h, g_o1h);
    cudaGetSymbolAddress((void**)&o1l, g_o1l);
    cudaGetSymbolAddress((void**)&w1h, g_w1h);
    cudaGetSymbolAddress((void**)&w1l, g_w1l);
    cudaGetSymbolAddress((void**)&w2h, g_w2h);
    cudaGetSymbolAddress((void**)&w2l, g_w2l);

    const int GAT1_SMEM = NPG * CH * 4 + 2 * NPG * 4 + (NPG + 1) * 4 + NE * 2;
    const int GAT2_SMEM = (NPG * CH + 4 * NPG + 2 * CH + 4) * 4 + (NPG + 1) * 4 + NE * 2;
    const int GEMM_SMEM = 3 * 2 * 128 * 128;
    cudaFuncSetAttribute(gat_agg1, cudaFuncAttributeMaxDynamicSharedMemorySize, GAT1_SMEM);
    cudaFuncSetAttribute(gat2_head, cudaFuncAttributeMaxDynamicSharedMemorySize, GAT2_SMEM);
    cudaFuncSetAttribute(gemm_hmma, cudaFuncAttributeMaxDynamicSharedMemorySize, GEMM_SMEM);

    // fused prep (x split + W splits + CSR + loss zero)
    prep<<<6144, 256>>>(x, xh, xl, W1, W2, es, ed, out + (out_size - 1));

    // layer 1: [NN,768] x [768,512]
    gemm_hmma<<<dim3(4, 400, 1), 256, GEMM_SMEM>>>(xh, xl, w1h, w1l, h1, 512, 768, 768, 0);
    gat_agg1<<<dim3(GG, 4), 256, GAT1_SMEM>>>(h1, as1, ad1, b1, o1h, o1l);

    // layer 2: [NN,512] x [512,128], split-K=2 (partials summed in gat2_head)
    gemm_hmma<<<dim3(1, 400, 2), 256, GEMM_SMEM>>>(o1h, o1l, w2h, w2l, h2, 128, 512, 256,
                                                   (size_t)NN * CH);
    // fused layer-2 GAT + cluster softmax + loss + readout
    gat2_head<<<GG, 256, GAT2_SMEM>>>(h2, h2 + (size_t)NN * CH, as2, ad2, b2, Wc, bc,
                                      es, ed, Wf1, bf1, Wf2, bf2, out, out + (out_size - 1));
}

// round 13
// speedup vs baseline: 1.0105x; 1.0105x over previous
#include <cuda_runtime.h>
#include <cuda_bf16.h>
#include <math.h>
#include <stdint.h>

#define NN   51200
#define GG   256
#define NPG  200
#define EE   409600
#define EPG  1600
#define CH   128
#define NE   (EPG + NPG)   // edges per graph incl self-loops = 1800

// ---------------- scratch (device globals; no allocs allowed) ----------------
__device__ float g_h1[(size_t)NN * 512];
__device__ float g_h2[(size_t)NN * CH];
__device__ __nv_bfloat16 g_xh[(size_t)NN * 768];
__device__ __nv_bfloat16 g_xl[(size_t)NN * 768];
__device__ __nv_bfloat16 g_o1h[(size_t)NN * 512];
__device__ __nv_bfloat16 g_o1l[(size_t)NN * 512];
__device__ __nv_bfloat16 g_w1h[512 * 768];
__device__ __nv_bfloat16 g_w1l[512 * 768];
__device__ __nv_bfloat16 g_w2h[128 * 512];
__device__ __nv_bfloat16 g_w2l[128 * 512];
__device__ unsigned short g_csr[(size_t)GG * NE];
__device__ int g_csro[GG * (NPG + 1)];

#define SWZB(o) ((o) ^ (((o) >> 3) & 0x70))

// =============== fused prep: x split + W1/W2 split + CSR + loss init ===============
__global__ void prep(const float* __restrict__ x, __nv_bfloat16* __restrict__ xh,
                     __nv_bfloat16* __restrict__ xl,
                     const float* __restrict__ W1, const float* __restrict__ W2,
                     const int* __restrict__ es, const int* __restrict__ ed,
                     float* __restrict__ loss) {
    const int b = blockIdx.x, tid = threadIdx.x;
    if (b < 4096) {
        const size_t n4 = (size_t)NN * 768 / 4;
        size_t i = (size_t)b * 256 + tid;
        const size_t stride = 4096 * 256;
        for (; i < n4; i += stride) {
            float4 v = ((const float4*)x)[i];
            __nv_bfloat16 h0 = __float2bfloat16(v.x), h1 = __float2bfloat16(v.y);
            __nv_bfloat16 h2 = __float2bfloat16(v.z), h3 = __float2bfloat16(v.w);
            __nv_bfloat16 l0 = __float2bfloat16(v.x - __bfloat162float(h0));
            __nv_bfloat16 l1 = __float2bfloat16(v.y - __bfloat162float(h1));
            __nv_bfloat16 l2 = __float2bfloat16(v.z - __bfloat162float(h2));
            __nv_bfloat16 l3 = __float2bfloat16(v.w - __bfloat162float(h3));
            ((__nv_bfloat162*)xh)[2 * i]     = __halves2bfloat162(h0, h1);
            ((__nv_bfloat162*)xh)[2 * i + 1] = __halves2bfloat162(h2, h3);
            ((__nv_bfloat162*)xl)[2 * i]     = __halves2bfloat162(l0, l1);
            ((__nv_bfloat162*)xl)[2 * i + 1] = __halves2bfloat162(l2, l3);
        }
    } else if (b < 5888) {
        const bool w1 = (b < 5632);
        const int K = w1 ? 768 : 512, Nn = w1 ? 512 : 128;
        const float* W = w1 ? W1 : W2;
        __nv_bfloat16* hi = w1 ? g_w1h : g_w2h;
        __nv_bfloat16* lo = w1 ? g_w1l : g_w2l;
        int idx = (b - (w1 ? 4096 : 5632)) * 256 + tid;
        if (idx < Nn * K) {
            int n = idx / K, k = idx - n * K;
            float v = W[(size_t)k * Nn + n];
            __nv_bfloat16 h = __float2bfloat16(v);
            hi[idx] = h;
            lo[idx] = __float2bfloat16(v - __bfloat162float(h));
        }
    } else {
        const int g = b - 5888;
        if (g == 0 && tid == 0) *loss = 0.f;
        __shared__ int cnt[NPG + 1];
        __shared__ int cur[NPG];
        __shared__ unsigned short sd[NE];
        for (int i = tid; i <= NPG; i += blockDim.x) cnt[i] = 0;
        __syncthreads();
        for (int e = tid; e < NE; e += blockDim.x) {
            int d = (e < EPG) ? (ed[g * EPG + e] - g * NPG) : (e - EPG);
            sd[e] = (unsigned short)d;
            atomicAdd(&cnt[d], 1);
        }
        __syncthreads();
        if (tid == 0) {
            int run = 0;
            for (int i = 0; i < NPG; i++) {
                int c = cnt[i]; cnt[i] = run;
                g_csro[g * (NPG + 1) + i] = run;
                run += c;
            }
            g_csro[g * (NPG + 1) + NPG] = run;
        }
        __syncthreads();
        for (int i = tid; i < NPG; i += blockDim.x) cur[i] = cnt[i];
        __syncthreads();
        for (int e = tid; e < NE; e += blockDim.x) {
            int s = (e < EPG) ? (es[g * EPG + e] - g * NPG) : (e - EPG);
            int p = atomicAdd(&cur[sd[e]], 1);
            g_csr[(size_t)g * NE + p] = (unsigned short)s;
        }
    }
}

// ============================ HMMA split-bf16 GEMM (R7/R10 config) ============================
__device__ __forceinline__ void ldsm4(uint32_t addr, uint32_t& r0, uint32_t& r1,
                                      uint32_t& r2, uint32_t& r3) {
    asm volatile("ldmatrix.sync.aligned.m8n8.x4.shared.b16 {%0,%1,%2,%3}, [%4];"
                 : "=r"(r0), "=r"(r1), "=r"(r2), "=r"(r3) : "r"(addr));
}

// C[M x Nn] = A[M x K] * B[Nn x K]^T via Ahi*Bhi + Ahi*Blo + Alo*Bhi.
// CTA 128x128, KC=64, 3-stage cp.async ring, single barrier per chunk,
// prefetch overlapped with MMAs, SW128-swizzled rows, ldmatrix.x4, 2 CTA/SM.
__global__ void __launch_bounds__(256, 2)
gemm_hmma(const __nv_bfloat16* __restrict__ Ahi, const __nv_bfloat16* __restrict__ Alo,
          const __nv_bfloat16* __restrict__ Bhi, const __nv_bfloat16* __restrict__ Blo,
          float* __restrict__ C, int Nn, int K) {
    constexpr int TILE = 128 * 128;
    constexpr int STG  = 2 * TILE;
    extern __shared__ char smb[];
    uint32_t sb;
    asm("{ .reg .u64 tt; cvta.to.shared.u64 tt, %1; cvt.u32.u64 %0, tt; }"
        : "=r"(sb) : "l"(smb));
    const int tid = threadIdx.x, lane = tid & 31, wid = tid >> 5;
    const int g = lane >> 2, t = lane & 3;
    const int bm = blockIdx.y * 128, bn = blockIdx.x * 128;
    const int wm = (wid >> 1) * 32, wn = (wid & 1) * 64;
    const int nk = K >> 6, nch = 3 * nk;
    const int aoff = ((lane & 7) + ((lane >> 3) & 1) * 8) * 128 + (lane >> 4) * 16;
    const int boff = ((lane & 7) + ((lane >> 4) & 1) * 8) * 128 + ((lane >> 3) & 1) * 16;

    float acc[2][8][4];
#pragma unroll
    for (int mf = 0; mf < 2; mf++)
#pragma unroll
        for (int nf = 0; nf < 8; nf++)
#pragma unroll
            for (int j = 0; j < 4; j++) acc[mf][nf][j] = 0.f;

    auto prefetch = [&](int c) {
        int pass = (c >= 2 * nk) ? 2 : ((c >= nk) ? 1 : 0);
        int kk = (c - pass * nk) << 6;
        const __nv_bfloat16* As = (pass < 2) ? Ahi : Alo;
        const __nv_bfloat16* Bs = (pass == 1) ? Blo : Bhi;
        uint32_t st = sb + (c % 3) * STG;
        const __nv_bfloat16* Ag = As + (size_t)bm * K + kk;
        const __nv_bfloat16* Bg = Bs + (size_t)bn * K + kk;
#pragma unroll
        for (int u = 0; u < 4; u++) {
            int v = u * 256 + tid;
            int r = v >> 3, c16 = v & 7;
            asm volatile("cp.async.cg.shared.global [%0], [%1], 16;"
                         :: "r"(st + SWZB(r * 128 + c16 * 16)),
                            "l"(Ag + (size_t)r * K + c16 * 8) : "memory");
        }
#pragma unroll
        for (int u = 0; u < 4; u++) {
            int v = u * 256 + tid;
            int r = v >> 3, c16 = v & 7;
            asm volatile("cp.async.cg.shared.global [%0], [%1], 16;"
                         :: "r"(st + TILE + SWZB(r * 128 + c16 * 16)),
                            "l"(Bg + (size_t)r * K + c16 * 8) : "memory");
        }
        asm volatile("cp.async.commit_group;" ::: "memory");
    };

    prefetch(0);
    prefetch(1);
    for (int c = 0; c < nch; c++) {
        if (c == nch - 1)
            asm volatile("cp.async.wait_group 0;" ::: "memory");
        else
            asm volatile("cp.async.wait_group 1;" ::: "memory");
        __syncthreads();
        if (c + 2 < nch) prefetch(c + 2);
        const uint32_t ab = sb + (c % 3) * STG;
        const uint32_t bb = ab + TILE;
#pragma unroll
        for (int ks = 0; ks < 4; ks++) {
            uint32_t af[2][4], bf[8][2];
#pragma unroll
            for (int mf = 0; mf < 2; mf++)
                ldsm4(ab + SWZB((wm + mf * 16) * 128 + ks * 32 + aoff),
                      af[mf][0], af[mf][1], af[mf][2], af[mf][3]);
#pragma unroll
            for (int nf2 = 0; nf2 < 4; nf2++)
                ldsm4(bb + SWZB((wn + nf2 * 16) * 128 + ks * 32 + boff),
                      bf[2 * nf2][0], bf[2 * nf2][1], bf[2 * nf2 + 1][0], bf[2 * nf2 + 1][1]);
#pragma unroll
            for (int mf = 0; mf < 2; mf++)
#pragma unroll
                for (int nf = 0; nf < 8; nf++) {
                    asm volatile(
                        "mma.sync.aligned.m16n8k16.row.col.f32.bf16.bf16.f32 "
                        "{%0,%1,%2,%3}, {%4,%5,%6,%7}, {%8,%9}, {%0,%1,%2,%3};"
                        : "+f"(acc[mf][nf][0]), "+f"(acc[mf][nf][1]),
                          "+f"(acc[mf][nf][2]), "+f"(acc[mf][nf][3])
                        : "r"(af[mf][0]), "r"(af[mf][1]), "r"(af[mf][2]), "r"(af[mf][3]),
                          "r"(bf[nf][0]), "r"(bf[nf][1]));
                }
        }
    }

#pragma unroll
    for (int mf = 0; mf < 2; mf++)
#pragma unroll
        for (int nf = 0; nf < 8; nf++) {
            int row = bm + wm + mf * 16 + g;
            int col = bn + wn + nf * 8 + t * 2;
            *(float2*)&C[(size_t)row * Nn + col] =
                make_float2(acc[mf][nf][0], acc[mf][nf][1]);
            *(float2*)&C[(size_t)(row + 8) * Nn + col] =
                make_float2(acc[mf][nf][2], acc[mf][nf][3]);
        }
}

// ====== layer-1 GAT: dots + softmax + aggregate -> bf16 hi/lo, block per (graph, head) ======
__global__ void gat_agg1(const float* __restrict__ h, const float* __restrict__ a_s,
                         const float* __restrict__ a_d, const float* __restrict__ bias,
                         __nv_bfloat16* __restrict__ outh, __nv_bfloat16* __restrict__ outl) {
    extern __shared__ float smem[];
    float* hb  = smem;                       // NPG*CH
    float* asr = hb + NPG * CH;
    float* adr = asr + NPG;
    int* soff  = (int*)(adr + NPG);
    unsigned short* ssrc = (unsigned short*)(soff + NPG + 1);

    const int g = blockIdx.x, hd = blockIdx.y;
    const int tid = threadIdx.x, wid = tid >> 5, lane = tid & 31;
    const int base = g * NPG;

    for (int i = tid; i < NPG * (CH / 4); i += blockDim.x) {
        int r = i / (CH / 4), c4 = (i % (CH / 4)) * 4;
        *(float4*)&hb[r * CH + c4] =
            *(const float4*)(h + (size_t)(base + r) * 512 + hd * CH + c4);
    }
    for (int i = tid; i <= NPG; i += blockDim.x) soff[i] = g_csro[g * (NPG + 1) + i];
    for (int i = tid; i < NE / 2; i += blockDim.x)
        ((uint32_t*)ssrc)[i] = ((const uint32_t*)(g_csr + (size_t)g * NE))[i];
    __syncthreads();

    {
        float4 s4 = *(const float4*)(a_s + hd * CH + lane * 4);
        float4 d4 = *(const float4*)(a_d + hd * CH + lane * 4);
        for (int r = wid; r < NPG; r += 8) {
            float4 v = *(float4*)&hb[r * CH + lane * 4];
            float ps = v.x * s4.x + v.y * s4.y + v.z * s4.z + v.w * s4.w;
            float pd = v.x * d4.x + v.y * d4.y + v.z * d4.z + v.w * d4.w;
#pragma unroll
            for (int o = 16; o; o >>= 1) {
                ps += __shfl_xor_sync(0xffffffffu, ps, o);
                pd += __shfl_xor_sync(0xffffffffu, pd, o);
            }
            if (lane == 0) { asr[r] = ps; adr[r] = pd; }
        }
    }
    __syncthreads();

    for (int d = wid; d < NPG; d += 8) {
        const int j0 = soff[d], j1 = soff[d + 1];
        const float add = adr[d];
        float m = -1e30f;
        for (int j = j0; j < j1; j++) {
            float l = asr[ssrc[j]] + add;
            l = l > 0.f ? l : 0.2f * l;
            m = fmaxf(m, l);
        }
        float sum = 0.f;
        float4 acc = make_float4(0.f, 0.f, 0.f, 0.f);
        for (int j = j0; j < j1; j++) {
            int s = ssrc[j];
            float l = asr[s] + add;
            l = l > 0.f ? l : 0.2f * l;
            float e = expf(l - m);
            sum += e;
            float4 hv = *(float4*)&hb[s * CH + lane * 4];
            acc.x += e * hv.x; acc.y += e * hv.y;
            acc.z += e * hv.z; acc.w += e * hv.w;
        }
        float inv = 1.f / (sum + 1e-16f);
        float4 b4 = *(const float4*)(bias + hd * CH + lane * 4);
        acc.x = fmaxf(acc.x * inv + b4.x, 0.f);
        acc.y = fmaxf(acc.y * inv + b4.y, 0.f);
        acc.z = fmaxf(acc.z * inv + b4.z, 0.f);
        acc.w = fmaxf(acc.w * inv + b4.w, 0.f);
        size_t o = (size_t)(base + d) * 512 + hd * CH + lane * 4;
        __nv_bfloat16 h0 = __float2bfloat16(acc.x), h1 = __float2bfloat16(acc.y);
        __nv_bfloat16 h2 = __float2bfloat16(acc.z), h3 = __float2bfloat16(acc.w);
        *(__nv_bfloat162*)(outh + o)     = __halves2bfloat162(h0, h1);
        *(__nv_bfloat162*)(outh + o + 2) = __halves2bfloat162(h2, h3);
        __nv_bfloat16 l0 = __float2bfloat16(acc.x - __bfloat162float(h0));
        __nv_bfloat16 l1 = __float2bfloat16(acc.y - __bfloat162float(h1));
        __nv_bfloat16 l2 = __float2bfloat16(acc.z - __bfloat162float(h2));
        __nv_bfloat16 l3 = __float2bfloat16(acc.w - __bfloat162float(h3));
        *(__nv_bfloat162*)(outl + o)     = __halves2bfloat162(l0, l1);
        *(__nv_bfloat162*)(outl + o + 2) = __halves2bfloat162(l2, l3);
    }
}

// ====== fused layer-2 GAT + cluster softmax + aggregate loss + readout MLP ======
// One block per graph.
__global__ void gat2_head(const float* __restrict__ h2,
                          const float* __restrict__ a_s, const float* __restrict__ a_d,
                          const float* __restrict__ bias,
                          const float* __restrict__ Wc, const float* __restrict__ bc,
                          const int* __restrict__ es, const int* __restrict__ ed,
                          const float* __restrict__ Wf1, const float* __restrict__ bf1,
                          const float* __restrict__ Wf2, const float* __restrict__ bf2,
                          float* __restrict__ out, float* __restrict__ loss) {
    extern __shared__ float smem[];
    float* hb  = smem;                        // NPG*CH
    float* asr = hb + NPG * CH;               // NPG
    float* adr = asr + NPG;                   // NPG
    float* s0a = adr + NPG;                   // NPG
    float* s1a = s0a + NPG;                   // NPG
    float* sub = s1a + NPG;                   // CH
    float* hid = sub + CH;                    // CH
    float* sa  = hid + CH;                    // 4
    int* soff  = (int*)(sa + 4);              // NPG+1
    unsigned short* ssrc = (unsigned short*)(soff + NPG + 1);  // NE

    const int g = blockIdx.x;
    const int tid = threadIdx.x, wid = tid >> 5, lane = tid & 31;
    const int base = g * NPG;

    for (int i = tid; i < NPG * (CH / 4); i += blockDim.x) {
        int r = i / (CH / 4), c4 = (i % (CH / 4)) * 4;
        *(float4*)&hb[r * CH + c4] =
            *(const float4*)(h2 + (size_t)(base + r) * CH + c4);
    }
    for (int i = tid; i <= NPG; i += blockDim.x) soff[i] = g_csro[g * (NPG + 1) + i];
    for (int i = tid; i < NE / 2; i += blockDim.x)
        ((uint32_t*)ssrc)[i] = ((const uint32_t*)(g_csr + (size_t)g * NE))[i];
    if (tid < CH) sub[tid] = 0.f;
    if (tid < 4) sa[tid] = 0.f;
    __syncthreads();

    {
        float4 s4 = *(const float4*)(a_s + lane * 4);
        float4 d4 = *(const float4*)(a_d + lane * 4);
        for (int r = wid; r < NPG; r += 8) {
            float4 v = *(float4*)&hb[r * CH + lane * 4];
            float ps = v.x * s4.x + v.y * s4.y + v.z * s4.z + v.w * s4.w;
            float pd = v.x * d4.x + v.y * d4.y + v.z * d4.z + v.w * d4.w;
#pragma unroll
            for (int o = 16; o; o >>= 1) {
                ps += __shfl_xor_sync(0xffffffffu, ps, o);
                pd += __shfl_xor_sync(0xffffffffu, pd, o);
            }
            if (lane == 0) { asr[r] = ps; adr[r] = pd; }
        }
    }
    __syncthreads();

    float2 w01[4];
#pragma unroll
    for (int j = 0; j < 4; j++)
        w01[j] = *(const float2*)(Wc + (lane * 4 + j) * 2);
    const float bc0 = bc[0], bc1 = bc[1];
    const float4 b4 = *(const float4*)(bias + lane * 4);

    for (int d = wid; d < NPG; d += 8) {
        const int j0 = soff[d], j1 = soff[d + 1];
        const float add = adr[d];
        float m = -1e30f;
        for (int j = j0; j < j1; j++) {
            float l = asr[ssrc[j]] + add;
            l = l > 0.f ? l : 0.2f * l;
            m = fmaxf(m, l);
        }
        float sum = 0.f;
        float4 acc = make_float4(0.f, 0.f, 0.f, 0.f);
        for (int j = j0; j < j1; j++) {
            int s = ssrc[j];
            float l = asr[s] + add;
            l = l > 0.f ? l : 0.2f * l;
            float e = expf(l - m);
            sum += e;
            float4 hv = *(float4*)&hb[s * CH + lane * 4];
            acc.x += e * hv.x; acc.y += e * hv.y;
            acc.z += e * hv.z; acc.w += e * hv.w;
        }
        float inv = 1.f / (sum + 1e-16f);
        acc.x = fmaxf(acc.x * inv + b4.x, 0.f);
        acc.y = fmaxf(acc.y * inv + b4.y, 0.f);
        acc.z = fmaxf(acc.z * inv + b4.z, 0.f);
        acc.w = fmaxf(acc.w * inv + b4.w, 0.f);
        // cluster softmax S = softmax(o2 @ Wc + bc)
        float p0 = acc.x * w01[0].x + acc.y * w01[1].x + acc.z * w01[2].x + acc.w * w01[3].x;
        float p1 = acc.x * w01[0].y + acc.y * w01[1].y + acc.z * w01[2].y + acc.w * w01[3].y;
#pragma unroll
        for (int o = 16; o; o >>= 1) {
            p0 += __shfl_xor_sync(0xffffffffu, p0, o);
            p1 += __shfl_xor_sync(0xffffffffu, p1, o);
        }
        float z0 = p0 + bc0, z1 = p1 + bc1;
        float mm = fmaxf(z0, z1);
        float e0 = expf(z0 - mm), e1 = expf(z1 - mm);
        float is = 1.f / (e0 + e1);
        float s0v = e0 * is, s1v = e1 * is;
        if (lane == 0) { s0a[d] = s0v; s1a[d] = s1v; }
        // sub[c] += S0[d] * o2[d][c]  (spread-bank smem atomics)
        atomicAdd(&sub[lane * 4 + 0], s0v * acc.x);
        atomicAdd(&sub[lane * 4 + 1], s0v * acc.y);
        atomicAdd(&sub[lane * 4 + 2], s0v * acc.z);
        atomicAdd(&sub[lane * 4 + 3], s0v * acc.w);
    }
    __syncthreads();

    // aggregate loss over original edges (S from smem)
    {
        float a00 = 0.f, a01 = 0.f, a10 = 0.f, a11 = 0.f;
        for (int e = tid; e < EPG; e += blockDim.x) {
            int so = es[g * EPG + e] - base, dn = ed[g * EPG + e] - base;
            float ss0 = s0a[so], ss1 = s1a[so];
            float d0 = s0a[dn], d1 = s1a[dn];
            a00 += ss0 * d0; a01 += ss0 * d1; a10 += ss1 * d0; a11 += ss1 * d1;
        }
#pragma unroll
        for (int o = 16; o; o >>= 1) {
            a00 += __shfl_xor_sync(0xffffffffu, a00, o);
            a01 += __shfl_xor_sync(0xffffffffu, a01, o);
            a10 += __shfl_xor_sync(0xffffffffu, a10, o);
            a11 += __shfl_xor_sync(0xffffffffu, a11, o);
        }
        if (lane == 0) {
            atomicAdd(&sa[0], a00); atomicAdd(&sa[1], a01);
            atomicAdd(&sa[2], a10); atomicAdd(&sa[3], a11);
        }
    }
    __syncthreads();
    if (tid == 0) {
        float r0 = fmaxf(fabsf(sa[0]) + fabsf(sa[1]), 1e-5f);
        float r1 = fmaxf(fabsf(sa[2]) + fabsf(sa[3]), 1e-5f);
        float d0 = sa[0] / r0 - 1.f, d1 = sa[3] / r1 - 1.f;
        float lg = 0.5f * (d0 * d0 + d1 * d1);
        atomicAdd(loss, lg * (1.f / (float)GG));
    }

    // readout MLP: relu(sub @ Wf1 + bf1) @ Wf2 + bf2
    if (tid < CH) {
        float hh = bf1[tid];
        for (int c = 0; c < CH; c++) hh += sub[c] * Wf1[c * CH + tid];
        hid[tid] = fmaxf(hh, 0.f);
    }
    __syncthreads();
    int w = tid >> 5;
    if (w < 2) {
        float p = 0.f;
        for (int j = lane; j < CH; j += 32) p += hid[j] * Wf2[j * 2 + w];
#pragma unroll
        for (int o = 16; o; o >>= 1) p += __shfl_down_sync(0xffffffffu, p, o);
        if (lane == 0) out[g * 2 + w] = p + bf2[w];
    }
}

// ============================ launcher ============================
extern "C" void kernel_launch(void* const* d_in, const int* in_sizes, int n_in,
                              void* d_out, int out_size) {
    const float* x   = (const float*)d_in[0];
    const int*   ei  = (const int*)d_in[1];
    const float* W1  = (const float*)d_in[3];
    const float* as1 = (const float*)d_in[4];
    const float* ad1 = (const float*)d_in[5];
    const float* b1  = (const float*)d_in[6];
    const float* W2  = (const float*)d_in[7];
    const float* as2 = (const float*)d_in[8];
    const float* ad2 = (const float*)d_in[9];
    const float* b2  = (const float*)d_in[10];
    const float* Wc  = (const float*)d_in[11];
    const float* bc  = (const float*)d_in[12];
    const float* Wf1 = (const float*)d_in[13];
    const float* bf1 = (const float*)d_in[14];
    const float* Wf2 = (const float*)d_in[15];
    const float* bf2 = (const float*)d_in[16];
    const int* es = ei;
    const int* ed = ei + EE;
    float* out = (float*)d_out;

    float *h1, *h2;
    __nv_bfloat16 *xh, *xl, *o1h, *o1l, *w1h, *w1l, *w2h, *w2l;
    cudaGetSymbolAddress((void**)&h1, g_h1);
    cudaGetSymbolAddress((void**)&h2, g_h2);
    cudaGetSymbolAddress((void**)&xh, g_xh);
    cudaGetSymbolAddress((void**)&xl, g_xl);
    cudaGetSymbolAddress((void**)&o1h, g_o1h);
    cudaGetSymbolAddress((void**)&o1l, g_o1l);
    cudaGetSymbolAddress((void**)&w1h, g_w1h);
    cudaGetSymbolAddress((void**)&w1l, g_w1l);
    cudaGetSymbolAddress((void**)&w2h, g_w2h);
    cudaGetSymbolAddress((void**)&w2l, g_w2l);

    const int GAT1_SMEM = NPG * CH * 4 + 2 * NPG * 4 + (NPG + 1) * 4 + NE * 2;
    const int GAT2_SMEM = (NPG * CH + 4 * NPG + 2 * CH + 4) * 4 + (NPG + 1) * 4 + NE * 2;
    const int GEMM_SMEM = 3 * 2 * 128 * 128;
    cudaFuncSetAttribute(gat_agg1, cudaFuncAttributeMaxDynamicSharedMemorySize, GAT1_SMEM);
    cudaFuncSetAttribute(gat2_head, cudaFuncAttributeMaxDynamicSharedMemorySize, GAT2_SMEM);
    cudaFuncSetAttribute(gemm_hmma, cudaFuncAttributeMaxDynamicSharedMemorySize, GEMM_SMEM);

    // fused prep (x split + W splits + CSR + loss zero)
    prep<<<6144, 256>>>(x, xh, xl, W1, W2, es, ed, out + (out_size - 1));

    // layer 1: [NN,768] x [768,512]
    gemm_hmma<<<dim3(4, 400), 256, GEMM_SMEM>>>(xh, xl, w1h, w1l, h1, 512, 768);
    gat_agg1<<<dim3(GG, 4), 256, GAT1_SMEM>>>(h1, as1, ad1, b1, o1h, o1l);

    // layer 2: [NN,512] x [512,128]
    gemm_hmma<<<dim3(1, 400), 256, GEMM_SMEM>>>(o1h, o1l, w2h, w2l, h2, 128, 512);

    // fused layer-2 GAT + cluster softmax + loss + readout
    gat2_head<<<GG, 256, GAT2_SMEM>>>(h2, as2, ad2, b2, Wc, bc,
                                      es, ed, Wf1, bf1, Wf2, bf2, out, out + (out_size - 1));
}

// round 14
// speedup vs baseline: 1.0163x; 1.0057x over previous
#include <cuda_runtime.h>
#include <cuda_bf16.h>
#include <math.h>
#include <stdint.h>

#define NN   51200
#define GG   256
#define NPG  200
#define EE   409600
#define EPG  1600
#define CH   128
#define NE   (EPG + NPG)   // edges per graph incl self-loops = 1800

// ---------------- scratch (device globals; no allocs allowed) ----------------
__device__ float g_h1[(size_t)NN * 512];
__device__ float g_h2[(size_t)NN * CH];
__device__ float g_o2[(size_t)NN * CH];
__device__ __nv_bfloat16 g_xh[(size_t)NN * 768];
__device__ __nv_bfloat16 g_xl[(size_t)NN * 768];
__device__ __nv_bfloat16 g_o1h[(size_t)NN * 512];
__device__ __nv_bfloat16 g_o1l[(size_t)NN * 512];
__device__ __nv_bfloat16 g_w1h[512 * 768];
__device__ __nv_bfloat16 g_w1l[512 * 768];
__device__ __nv_bfloat16 g_w2h[128 * 512];
__device__ __nv_bfloat16 g_w2l[128 * 512];
__device__ float g_S[NN * 2];
__device__ unsigned short g_csr[(size_t)GG * NE];
__device__ int g_csro[GG * (NPG + 1)];

#define SWZB(o) ((o) ^ (((o) >> 3) & 0x70))

// =============== fused prep: x split + W1/W2 split + CSR + loss init ===============
__global__ void prep(const float* __restrict__ x, __nv_bfloat16* __restrict__ xh,
                     __nv_bfloat16* __restrict__ xl,
                     const float* __restrict__ W1, const float* __restrict__ W2,
                     const int* __restrict__ es, const int* __restrict__ ed,
                     float* __restrict__ loss) {
    const int b = blockIdx.x, tid = threadIdx.x;
    if (b < 4096) {
        const size_t n4 = (size_t)NN * 768 / 4;
        size_t i = (size_t)b * 256 + tid;
        const size_t stride = 4096 * 256;
        for (; i < n4; i += stride) {
            float4 v = ((const float4*)x)[i];
            __nv_bfloat16 h0 = __float2bfloat16(v.x), h1 = __float2bfloat16(v.y);
            __nv_bfloat16 h2 = __float2bfloat16(v.z), h3 = __float2bfloat16(v.w);
            __nv_bfloat16 l0 = __float2bfloat16(v.x - __bfloat162float(h0));
            __nv_bfloat16 l1 = __float2bfloat16(v.y - __bfloat162float(h1));
            __nv_bfloat16 l2 = __float2bfloat16(v.z - __bfloat162float(h2));
            __nv_bfloat16 l3 = __float2bfloat16(v.w - __bfloat162float(h3));
            ((__nv_bfloat162*)xh)[2 * i]     = __halves2bfloat162(h0, h1);
            ((__nv_bfloat162*)xh)[2 * i + 1] = __halves2bfloat162(h2, h3);
            ((__nv_bfloat162*)xl)[2 * i]     = __halves2bfloat162(l0, l1);
            ((__nv_bfloat162*)xl)[2 * i + 1] = __halves2bfloat162(l2, l3);
        }
    } else if (b < 5888) {
        const bool w1 = (b < 5632);
        const int K = w1 ? 768 : 512, Nn = w1 ? 512 : 128;
        const float* W = w1 ? W1 : W2;
        __nv_bfloat16* hi = w1 ? g_w1h : g_w2h;
        __nv_bfloat16* lo = w1 ? g_w1l : g_w2l;
        int idx = (b - (w1 ? 4096 : 5632)) * 256 + tid;
        if (idx < Nn * K) {
            int n = idx / K, k = idx - n * K;
            float v = W[(size_t)k * Nn + n];
            __nv_bfloat16 h = __float2bfloat16(v);
            hi[idx] = h;
            lo[idx] = __float2bfloat16(v - __bfloat162float(h));
        }
    } else {
        const int g = b - 5888;
        if (g == 0 && tid == 0) *loss = 0.f;
        __shared__ int cnt[NPG + 1];
        __shared__ int cur[NPG];
        __shared__ unsigned short sd[NE];
        for (int i = tid; i <= NPG; i += blockDim.x) cnt[i] = 0;
        __syncthreads();
        for (int e = tid; e < NE; e += blockDim.x) {
            int d = (e < EPG) ? (ed[g * EPG + e] - g * NPG) : (e - EPG);
            sd[e] = (unsigned short)d;
            atomicAdd(&cnt[d], 1);
        }
        __syncthreads();
        if (tid == 0) {
            int run = 0;
            for (int i = 0; i < NPG; i++) {
                int c = cnt[i]; cnt[i] = run;
                g_csro[g * (NPG + 1) + i] = run;
                run += c;
            }
            g_csro[g * (NPG + 1) + NPG] = run;
        }
        __syncthreads();
        for (int i = tid; i < NPG; i += blockDim.x) cur[i] = cnt[i];
        __syncthreads();
        for (int e = tid; e < NE; e += blockDim.x) {
            int s = (e < EPG) ? (es[g * EPG + e] - g * NPG) : (e - EPG);
            int p = atomicAdd(&cur[sd[e]], 1);
            g_csr[(size_t)g * NE + p] = (unsigned short)s;
        }
    }
}

// ============================ HMMA split-bf16 GEMM (128x128 tiles) ============================
__device__ __forceinline__ void ldsm4(uint32_t addr, uint32_t& r0, uint32_t& r1,
                                      uint32_t& r2, uint32_t& r3) {
    asm volatile("ldmatrix.sync.aligned.m8n8.x4.shared.b16 {%0,%1,%2,%3}, [%4];"
                 : "=r"(r0), "=r"(r1), "=r"(r2), "=r"(r3) : "r"(addr));
}

// C[M x Nn] = A[M x K] * B[Nn x K]^T via Ahi*Bhi + Ahi*Blo + Alo*Bhi.
__global__ void __launch_bounds__(256, 2)
gemm_hmma(const __nv_bfloat16* __restrict__ Ahi, const __nv_bfloat16* __restrict__ Alo,
          const __nv_bfloat16* __restrict__ Bhi, const __nv_bfloat16* __restrict__ Blo,
          float* __restrict__ C, int Nn, int K) {
    constexpr int TILE = 128 * 128;
    constexpr int STG  = 2 * TILE;
    extern __shared__ char smb[];
    uint32_t sb;
    asm("{ .reg .u64 tt; cvta.to.shared.u64 tt, %1; cvt.u32.u64 %0, tt; }"
        : "=r"(sb) : "l"(smb));
    const int tid = threadIdx.x, lane = tid & 31, wid = tid >> 5;
    const int g = lane >> 2, t = lane & 3;
    const int bm = blockIdx.y * 128, bn = blockIdx.x * 128;
    const int wm = (wid >> 1) * 32, wn = (wid & 1) * 64;
    const int nk = K >> 6, nch = 3 * nk;
    const int aoff = ((lane & 7) + ((lane >> 3) & 1) * 8) * 128 + (lane >> 4) * 16;
    const int boff = ((lane & 7) + ((lane >> 4) & 1) * 8) * 128 + ((lane >> 3) & 1) * 16;

    float acc[2][8][4];
#pragma unroll
    for (int mf = 0; mf < 2; mf++)
#pragma unroll
        for (int nf = 0; nf < 8; nf++)
#pragma unroll
            for (int j = 0; j < 4; j++) acc[mf][nf][j] = 0.f;

    auto prefetch = [&](int c) {
        int pass = (c >= 2 * nk) ? 2 : ((c >= nk) ? 1 : 0);
        int kk = (c - pass * nk) << 6;
        const __nv_bfloat16* As = (pass < 2) ? Ahi : Alo;
        const __nv_bfloat16* Bs = (pass == 1) ? Blo : Bhi;
        uint32_t st = sb + (c % 3) * STG;
        const __nv_bfloat16* Ag = As + (size_t)bm * K + kk;
        const __nv_bfloat16* Bg = Bs + (size_t)bn * K + kk;
#pragma unroll
        for (int u = 0; u < 4; u++) {
            int v = u * 256 + tid;
            int r = v >> 3, c16 = v & 7;
            asm volatile("cp.async.cg.shared.global [%0], [%1], 16;"
                         :: "r"(st + SWZB(r * 128 + c16 * 16)),
                            "l"(Ag + (size_t)r * K + c16 * 8) : "memory");
        }
#pragma unroll
        for (int u = 0; u < 4; u++) {
            int v = u * 256 + tid;
            int r = v >> 3, c16 = v & 7;
            asm volatile("cp.async.cg.shared.global [%0], [%1], 16;"
                         :: "r"(st + TILE + SWZB(r * 128 + c16 * 16)),
                            "l"(Bg + (size_t)r * K + c16 * 8) : "memory");
        }
        asm volatile("cp.async.commit_group;" ::: "memory");
    };

    prefetch(0);
    prefetch(1);
    for (int c = 0; c < nch; c++) {
        if (c == nch - 1)
            asm volatile("cp.async.wait_group 0;" ::: "memory");
        else
            asm volatile("cp.async.wait_group 1;" ::: "memory");
        __syncthreads();
        if (c + 2 < nch) prefetch(c + 2);
        const uint32_t ab = sb + (c % 3) * STG;
        const uint32_t bb = ab + TILE;
#pragma unroll
        for (int ks = 0; ks < 4; ks++) {
            uint32_t af[2][4], bf[8][2];
#pragma unroll
            for (int mf = 0; mf < 2; mf++)
                ldsm4(ab + SWZB((wm + mf * 16) * 128 + ks * 32 + aoff),
                      af[mf][0], af[mf][1], af[mf][2], af[mf][3]);
#pragma unroll
            for (int nf2 = 0; nf2 < 4; nf2++)
                ldsm4(bb + SWZB((wn + nf2 * 16) * 128 + ks * 32 + boff),
                      bf[2 * nf2][0], bf[2 * nf2][1], bf[2 * nf2 + 1][0], bf[2 * nf2 + 1][1]);
#pragma unroll
            for (int mf = 0; mf < 2; mf++)
#pragma unroll
                for (int nf = 0; nf < 8; nf++) {
                    asm volatile(
                        "mma.sync.aligned.m16n8k16.row.col.f32.bf16.bf16.f32 "
                        "{%0,%1,%2,%3}, {%4,%5,%6,%7}, {%8,%9}, {%0,%1,%2,%3};"
                        : "+f"(acc[mf][nf][0]), "+f"(acc[mf][nf][1]),
                          "+f"(acc[mf][nf][2]), "+f"(acc[mf][nf][3])
                        : "r"(af[mf][0]), "r"(af[mf][1]), "r"(af[mf][2]), "r"(af[mf][3]),
                          "r"(bf[nf][0]), "r"(bf[nf][1]));
                }
        }
    }

#pragma unroll
    for (int mf = 0; mf < 2; mf++)
#pragma unroll
        for (int nf = 0; nf < 8; nf++) {
            int row = bm + wm + mf * 16 + g;
            int col = bn + wn + nf * 8 + t * 2;
            *(float2*)&C[(size_t)row * Nn + col] =
                make_float2(acc[mf][nf][0], acc[mf][nf][1]);
            *(float2*)&C[(size_t)(row + 8) * Nn + col] =
                make_float2(acc[mf][nf][2], acc[mf][nf][3]);
        }
}

// ============ 64x128-tile variant (better wave balance for small-N GEMM2) ============
__global__ void __launch_bounds__(256, 2)
gemm_hmma64(const __nv_bfloat16* __restrict__ Ahi, const __nv_bfloat16* __restrict__ Alo,
            const __nv_bfloat16* __restrict__ Bhi, const __nv_bfloat16* __restrict__ Blo,
            float* __restrict__ C, int Nn, int K) {
    constexpr int ATILE = 64 * 128;    // 8192 bytes
    constexpr int BTILE = 128 * 128;   // 16384 bytes
    constexpr int STG   = ATILE + BTILE;  // 24576 bytes
    extern __shared__ char smb[];
    uint32_t sb;
    asm("{ .reg .u64 tt; cvta.to.shared.u64 tt, %1; cvt.u32.u64 %0, tt; }"
        : "=r"(sb) : "l"(smb));
    const int tid = threadIdx.x, lane = tid & 31, wid = tid >> 5;
    const int g = lane >> 2, t = lane & 3;
    const int bm = blockIdx.y * 64, bn = blockIdx.x * 128;
    const int wm = (wid >> 2) * 32, wn = (wid & 3) * 32;
    const int nk = K >> 6, nch = 3 * nk;
    const int aoff = ((lane & 7) + ((lane >> 3) & 1) * 8) * 128 + (lane >> 4) * 16;
    const int boff = ((lane & 7) + ((lane >> 4) & 1) * 8) * 128 + ((lane >> 3) & 1) * 16;

    float acc[2][4][4];
#pragma unroll
    for (int mf = 0; mf < 2; mf++)
#pragma unroll
        for (int nf = 0; nf < 4; nf++)
#pragma unroll
            for (int j = 0; j < 4; j++) acc[mf][nf][j] = 0.f;

    auto prefetch = [&](int c) {
        int pass = (c >= 2 * nk) ? 2 : ((c >= nk) ? 1 : 0);
        int kk = (c - pass * nk) << 6;
        const __nv_bfloat16* As = (pass < 2) ? Ahi : Alo;
        const __nv_bfloat16* Bs = (pass == 1) ? Blo : Bhi;
        uint32_t st = sb + (c % 3) * STG;
        const __nv_bfloat16* Ag = As + (size_t)bm * K + kk;
        const __nv_bfloat16* Bg = Bs + (size_t)bn * K + kk;
#pragma unroll
        for (int u = 0; u < 2; u++) {      // 512 vectors / 256 threads
            int v = u * 256 + tid;
            int r = v >> 3, c16 = v & 7;
            asm volatile("cp.async.cg.shared.global [%0], [%1], 16;"
                         :: "r"(st + SWZB(r * 128 + c16 * 16)),
                            "l"(Ag + (size_t)r * K + c16 * 8) : "memory");
        }
#pragma unroll
        for (int u = 0; u < 4; u++) {      // 1024 vectors
            int v = u * 256 + tid;
            int r = v >> 3, c16 = v & 7;
            asm volatile("cp.async.cg.shared.global [%0], [%1], 16;"
                         :: "r"(st + ATILE + SWZB(r * 128 + c16 * 16)),
                            "l"(Bg + (size_t)r * K + c16 * 8) : "memory");
        }
        asm volatile("cp.async.commit_group;" ::: "memory");
    };

    prefetch(0);
    prefetch(1);
    for (int c = 0; c < nch; c++) {
        if (c == nch - 1)
            asm volatile("cp.async.wait_group 0;" ::: "memory");
        else
            asm volatile("cp.async.wait_group 1;" ::: "memory");
        __syncthreads();
        if (c + 2 < nch) prefetch(c + 2);
        const uint32_t ab = sb + (c % 3) * STG;
        const uint32_t bb = ab + ATILE;
#pragma unroll
        for (int ks = 0; ks < 4; ks++) {
            uint32_t af[2][4], bf[4][2];
#pragma unroll
            for (int mf = 0; mf < 2; mf++)
                ldsm4(ab + SWZB((wm + mf * 16) * 128 + ks * 32 + aoff),
                      af[mf][0], af[mf][1], af[mf][2], af[mf][3]);
#pragma unroll
            for (int nf2 = 0; nf2 < 2; nf2++)
                ldsm4(bb + SWZB((wn + nf2 * 16) * 128 + ks * 32 + boff),
                      bf[2 * nf2][0], bf[2 * nf2][1], bf[2 * nf2 + 1][0], bf[2 * nf2 + 1][1]);
#pragma unroll
            for (int mf = 0; mf < 2; mf++)
#pragma unroll
                for (int nf = 0; nf < 4; nf++) {
                    asm volatile(
                        "mma.sync.aligned.m16n8k16.row.col.f32.bf16.bf16.f32 "
                        "{%0,%1,%2,%3}, {%4,%5,%6,%7}, {%8,%9}, {%0,%1,%2,%3};"
                        : "+f"(acc[mf][nf][0]), "+f"(acc[mf][nf][1]),
                          "+f"(acc[mf][nf][2]), "+f"(acc[mf][nf][3])
                        : "r"(af[mf][0]), "r"(af[mf][1]), "r"(af[mf][2]), "r"(af[mf][3]),
                          "r"(bf[nf][0]), "r"(bf[nf][1]));
                }
        }
    }

#pragma unroll
    for (int mf = 0; mf < 2; mf++)
#pragma unroll
        for (int nf = 0; nf < 4; nf++) {
            int row = bm + wm + mf * 16 + g;
            int col = bn + wn + nf * 8 + t * 2;
            *(float2*)&C[(size_t)row * Nn + col] =
                make_float2(acc[mf][nf][0], acc[mf][nf][1]);
            *(float2*)&C[(size_t)(row + 8) * Nn + col] =
                make_float2(acc[mf][nf][2], acc[mf][nf][3]);
        }
}

// ====== fused GAT: dots + softmax + aggregate (+optional cluster softmax) ======
__global__ void gat_agg(const float* __restrict__ h, const float* __restrict__ a_s,
                        const float* __restrict__ a_d, const float* __restrict__ bias,
                        float* __restrict__ outf, __nv_bfloat16* __restrict__ outh,
                        __nv_bfloat16* __restrict__ outl,
                        const float* __restrict__ Wc, const float* __restrict__ bc,
                        float* __restrict__ S, int H, int stride) {
    extern __shared__ float smem[];
    float* hb  = smem;                       // NPG*CH
    float* asr = hb + NPG * CH;
    float* adr = asr + NPG;
    int* soff  = (int*)(adr + NPG);
    unsigned short* ssrc = (unsigned short*)(soff + NPG + 1);

    const int g = blockIdx.x, hd = blockIdx.y;
    const int tid = threadIdx.x, wid = tid >> 5, lane = tid & 31;
    const int base = g * NPG;

    for (int i = tid; i < NPG * (CH / 4); i += blockDim.x) {
        int r = i / (CH / 4), c4 = (i % (CH / 4)) * 4;
        *(float4*)&hb[r * CH + c4] =
            *(const float4*)(h + (size_t)(base + r) * stride + hd * CH + c4);
    }
    for (int i = tid; i <= NPG; i += blockDim.x) soff[i] = g_csro[g * (NPG + 1) + i];
    for (int i = tid; i < NE / 2; i += blockDim.x)
        ((uint32_t*)ssrc)[i] = ((const uint32_t*)(g_csr + (size_t)g * NE))[i];
    __syncthreads();

    {
        float4 s4 = *(const float4*)(a_s + hd * CH + lane * 4);
        float4 d4 = *(const float4*)(a_d + hd * CH + lane * 4);
        for (int r = wid; r < NPG; r += 8) {
            float4 v = *(float4*)&hb[r * CH + lane * 4];
            float ps = v.x * s4.x + v.y * s4.y + v.z * s4.z + v.w * s4.w;
            float pd = v.x * d4.x + v.y * d4.y + v.z * d4.z + v.w * d4.w;
#pragma unroll
            for (int o = 16; o; o >>= 1) {
                ps += __shfl_xor_sync(0xffffffffu, ps, o);
                pd += __shfl_xor_sync(0xffffffffu, pd, o);
            }
            if (lane == 0) { asr[r] = ps; adr[r] = pd; }
        }
    }
    __syncthreads();

    float2 w01[4];
    if (S) {
#pragma unroll
        for (int j = 0; j < 4; j++)
            w01[j] = *(const float2*)(Wc + (lane * 4 + j) * 2);
    }
    float bc0 = S ? bc[0] : 0.f, bc1 = S ? bc[1] : 0.f;

    for (int d = wid; d < NPG; d += 8) {
        const int j0 = soff[d], j1 = soff[d + 1];
        const float add = adr[d];
        float m = -1e30f;
        for (int j = j0; j < j1; j++) {
            float l = asr[ssrc[j]] + add;
            l = l > 0.f ? l : 0.2f * l;
            m = fmaxf(m, l);
        }
        float sum = 0.f;
        float4 acc = make_float4(0.f, 0.f, 0.f, 0.f);
        for (int j = j0; j < j1; j++) {
            int s = ssrc[j];
            float l = asr[s] + add;
            l = l > 0.f ? l : 0.2f * l;
            float e = expf(l - m);
            sum += e;
            float4 hv = *(float4*)&hb[s * CH + lane * 4];
            acc.x += e * hv.x; acc.y += e * hv.y;
            acc.z += e * hv.z; acc.w += e * hv.w;
        }
        float inv = 1.f / (sum + 1e-16f);
        float4 b4 = *(const float4*)(bias + hd * CH + lane * 4);
        acc.x = fmaxf(acc.x * inv + b4.x, 0.f);
        acc.y = fmaxf(acc.y * inv + b4.y, 0.f);
        acc.z = fmaxf(acc.z * inv + b4.z, 0.f);
        acc.w = fmaxf(acc.w * inv + b4.w, 0.f);
        size_t o = (size_t)(base + d) * stride + hd * CH + lane * 4;
        if (outf) *(float4*)(outf + o) = acc;
        if (outh) {
            __nv_bfloat16 h0 = __float2bfloat16(acc.x), h1 = __float2bfloat16(acc.y);
            __nv_bfloat16 h2 = __float2bfloat16(acc.z), h3 = __float2bfloat16(acc.w);
            *(__nv_bfloat162*)(outh + o)     = __halves2bfloat162(h0, h1);
            *(__nv_bfloat162*)(outh + o + 2) = __halves2bfloat162(h2, h3);
            __nv_bfloat16 l0 = __float2bfloat16(acc.x - __bfloat162float(h0));
            __nv_bfloat16 l1 = __float2bfloat16(acc.y - __bfloat162float(h1));
            __nv_bfloat16 l2 = __float2bfloat16(acc.z - __bfloat162float(h2));
            __nv_bfloat16 l3 = __float2bfloat16(acc.w - __bfloat162float(h3));
            *(__nv_bfloat162*)(outl + o)     = __halves2bfloat162(l0, l1);
            *(__nv_bfloat162*)(outl + o + 2) = __halves2bfloat162(l2, l3);
        }
        if (S) {
            float p0 = acc.x * w01[0].x + acc.y * w01[1].x + acc.z * w01[2].x + acc.w * w01[3].x;
            float p1 = acc.x * w01[0].y + acc.y * w01[1].y + acc.z * w01[2].y + acc.w * w01[3].y;
#pragma unroll
            for (int o2_ = 16; o2_; o2_ >>= 1) {
                p0 += __shfl_xor_sync(0xffffffffu, p0, o2_);
                p1 += __shfl_xor_sync(0xffffffffu, p1, o2_);
            }
            if (lane == 0) {
                float z0 = p0 + bc0, z1 = p1 + bc1;
                float mm = fmaxf(z0, z1);
                float e0 = expf(z0 - mm), e1 = expf(z1 - mm);
                float is = 1.f / (e0 + e1);
                S[(base + d) * 2] = e0 * is;
                S[(base + d) * 2 + 1] = e1 * is;
            }
        }
    }
}

// ============== merged head: aggregate loss + per-graph readout MLP ==============
__global__ void head_k(const float* __restrict__ S, const int* __restrict__ es,
                       const int* __restrict__ ed, const float* __restrict__ h2,
                       const float* __restrict__ Wf1, const float* __restrict__ bf1,
                       const float* __restrict__ Wf2, const float* __restrict__ bf2,
                       float* __restrict__ out, float* __restrict__ loss) {
    const int g = blockIdx.x, tid = threadIdx.x;   // 256 threads
    __shared__ float s0[NPG];
    __shared__ float sub[CH];
    __shared__ float hid[CH];
    __shared__ float sa[4];

    float a00 = 0.f, a01 = 0.f, a10 = 0.f, a11 = 0.f;
    for (int e = tid; e < EPG; e += blockDim.x) {
        int so = es[g * EPG + e], dn = ed[g * EPG + e];
        float ss0 = S[so * 2], ss1 = S[so * 2 + 1];
        float d0 = S[dn * 2], d1 = S[dn * 2 + 1];
        a00 += ss0 * d0; a01 += ss0 * d1; a10 += ss1 * d0; a11 += ss1 * d1;
    }
#pragma unroll
    for (int o = 16; o; o >>= 1) {
        a00 += __shfl_xor_sync(0xffffffffu, a00, o);
        a01 += __shfl_xor_sync(0xffffffffu, a01, o);
        a10 += __shfl_xor_sync(0xffffffffu, a10, o);
        a11 += __shfl_xor_sync(0xffffffffu, a11, o);
    }
    if (tid < 4) sa[tid] = 0.f;
    for (int i = tid; i < NPG; i += blockDim.x) s0[i] = S[(g * NPG + i) * 2];
    __syncthreads();
    if ((tid & 31) == 0) {
        atomicAdd(&sa[0], a00); atomicAdd(&sa[1], a01);
        atomicAdd(&sa[2], a10); atomicAdd(&sa[3], a11);
    }
    __syncthreads();
    if (tid == 0) {
        float r0 = fmaxf(fabsf(sa[0]) + fabsf(sa[1]), 1e-5f);
        float r1 = fmaxf(fabsf(sa[2]) + fabsf(sa[3]), 1e-5f);
        float d0 = sa[0] / r0 - 1.f, d1 = sa[3] / r1 - 1.f;
        float lg = 0.5f * (d0 * d0 + d1 * d1);
        atomicAdd(loss, lg * (1.f / (float)GG));
    }

    if (tid < CH) {
        float acc = 0.f;
        for (int n = 0; n < NPG; n++)
            acc += s0[n] * h2[(size_t)(g * NPG + n) * CH + tid];
        sub[tid] = acc;
    }
    __syncthreads();
    if (tid < CH) {
        float hh = bf1[tid];
        for (int c = 0; c < CH; c++) hh += sub[c] * Wf1[c * CH + tid];
        hid[tid] = fmaxf(hh, 0.f);
    }
    __syncthreads();
    int w = tid >> 5, lane = tid & 31;
    if (w < 2) {
        float p = 0.f;
        for (int j = lane; j < CH; j += 32) p += hid[j] * Wf2[j * 2 + w];
#pragma unroll
        for (int o = 16; o; o >>= 1) p += __shfl_down_sync(0xffffffffu, p, o);
        if (lane == 0) out[g * 2 + w] = p + bf2[w];
    }
}

// ============================ launcher ============================
extern "C" void kernel_launch(void* const* d_in, const int* in_sizes, int n_in,
                              void* d_out, int out_size) {
    const float* x   = (const float*)d_in[0];
    const int*   ei  = (const int*)d_in[1];
    const float* W1  = (const float*)d_in[3];
    const float* as1 = (const float*)d_in[4];
    const float* ad1 = (const float*)d_in[5];
    const float* b1  = (const float*)d_in[6];
    const float* W2  = (const float*)d_in[7];
    const float* as2 = (const float*)d_in[8];
    const float* ad2 = (const float*)d_in[9];
    const float* b2  = (const float*)d_in[10];
    const float* Wc  = (const float*)d_in[11];
    const float* bc  = (const float*)d_in[12];
    const float* Wf1 = (const float*)d_in[13];
    const float* bf1 = (const float*)d_in[14];
    const float* Wf2 = (const float*)d_in[15];
    const float* bf2 = (const float*)d_in[16];
    const int* es = ei;
    const int* ed = ei + EE;
    float* out = (float*)d_out;

    float *h1, *h2, *o2, *S;
    __nv_bfloat16 *xh, *xl, *o1h, *o1l, *w1h, *w1l, *w2h, *w2l;
    cudaGetSymbolAddress((void**)&h1, g_h1);
    cudaGetSymbolAddress((void**)&h2, g_h2);
    cudaGetSymbolAddress((void**)&o2, g_o2);
    cudaGetSymbolAddress((void**)&xh, g_xh);
    cudaGetSymbolAddress((void**)&xl, g_xl);
    cudaGetSymbolAddress((void**)&o1h, g_o1h);
    cudaGetSymbolAddress((void**)&o1l, g_o1l);
    cudaGetSymbolAddress((void**)&w1h, g_w1h);
    cudaGetSymbolAddress((void**)&w1l, g_w1l);
    cudaGetSymbolAddress((void**)&w2h, g_w2h);
    cudaGetSymbolAddress((void**)&w2l, g_w2l);
    cudaGetSymbolAddress((void**)&S, g_S);

    const int GAT_SMEM = NPG * CH * 4 + 2 * NPG * 4 + (NPG + 1) * 4 + NE * 2;
    const int GEMM_SMEM = 3 * 2 * 128 * 128;     // 98304
    const int GEMM64_SMEM = 3 * (64 + 128) * 128;  // 73728
    cudaFuncSetAttribute(gat_agg, cudaFuncAttributeMaxDynamicSharedMemorySize, GAT_SMEM);
    cudaFuncSetAttribute(gemm_hmma, cudaFuncAttributeMaxDynamicSharedMemorySize, GEMM_SMEM);
    cudaFuncSetAttribute(gemm_hmma64, cudaFuncAttributeMaxDynamicSharedMemorySize, GEMM64_SMEM);

    // fused prep (x split + W splits + CSR + loss zero)
    prep<<<6144, 256>>>(x, xh, xl, W1, W2, es, ed, out + (out_size - 1));

    // layer 1: [NN,768] x [768,512]
    gemm_hmma<<<dim3(4, 400), 256, GEMM_SMEM>>>(xh, xl, w1h, w1l, h1, 512, 768);
    gat_agg<<<dim3(GG, 4), 256, GAT_SMEM>>>(h1, as1, ad1, b1,
                                            nullptr, o1h, o1l,
                                            nullptr, nullptr, nullptr, 4, 512);
    // layer 2: [NN,512] x [512,128], 64-row tiles for wave balance
    gemm_hmma64<<<dim3(1, 800), 256, GEMM64_SMEM>>>(o1h, o1l, w2h, w2l, h2, 128, 512);
    gat_agg<<<dim3(GG, 1), 256, GAT_SMEM>>>(h2, as2, ad2, b2,
                                            o2, nullptr, nullptr,
                                            Wc, bc, S, 1, 128);
    // merged head
    head_k<<<GG, 256>>>(S, es, ed, o2, Wf1, bf1, Wf2, bf2, out, out + (out_size - 1));
}

// round 15
// speedup vs baseline: 1.0563x; 1.0394x over previous
#include <cuda_runtime.h>
#include <cuda_bf16.h>
#include <math.h>
#include <stdint.h>

#define NN   51200
#define GG   256
#define NPG  200
#define EE   409600
#define EPG  1600
#define CH   128
#define NE   (EPG + NPG)   // edges per graph incl self-loops = 1800

// ---------------- scratch (device globals; no allocs allowed) ----------------
__device__ float g_h1[(size_t)NN * 512];
__device__ float g_h2[(size_t)NN * CH];
__device__ float g_o2[(size_t)NN * CH];
__device__ __nv_bfloat16 g_xh[(size_t)NN * 768];
__device__ __nv_bfloat16 g_xl[(size_t)NN * 768];
__device__ __nv_bfloat16 g_o1h[(size_t)NN * 512];
__device__ __nv_bfloat16 g_o1l[(size_t)NN * 512];
__device__ __nv_bfloat16 g_w1h[512 * 768];
__device__ __nv_bfloat16 g_w1l[512 * 768];
__device__ __nv_bfloat16 g_w2h[128 * 512];
__device__ __nv_bfloat16 g_w2l[128 * 512];
__device__ float g_S[NN * 2];
__device__ unsigned short g_csr[(size_t)GG * NE];
__device__ int g_csro[GG * (NPG + 1)];

#define SWZB(o) ((o) ^ (((o) >> 3) & 0x70))

// =============== fused prep: x split + W1/W2 split + CSR + loss init ===============
__global__ void prep(const float* __restrict__ x, __nv_bfloat16* __restrict__ xh,
                     __nv_bfloat16* __restrict__ xl,
                     const float* __restrict__ W1, const float* __restrict__ W2,
                     const int* __restrict__ es, const int* __restrict__ ed,
                     float* __restrict__ loss) {
    const int b = blockIdx.x, tid = threadIdx.x;
    if (b < 4096) {
        const size_t n4 = (size_t)NN * 768 / 4;
        size_t i = (size_t)b * 256 + tid;
        const size_t stride = 4096 * 256;
        for (; i < n4; i += stride) {
            float4 v = ((const float4*)x)[i];
            __nv_bfloat16 h0 = __float2bfloat16(v.x), h1 = __float2bfloat16(v.y);
            __nv_bfloat16 h2 = __float2bfloat16(v.z), h3 = __float2bfloat16(v.w);
            __nv_bfloat16 l0 = __float2bfloat16(v.x - __bfloat162float(h0));
            __nv_bfloat16 l1 = __float2bfloat16(v.y - __bfloat162float(h1));
            __nv_bfloat16 l2 = __float2bfloat16(v.z - __bfloat162float(h2));
            __nv_bfloat16 l3 = __float2bfloat16(v.w - __bfloat162float(h3));
            ((__nv_bfloat162*)xh)[2 * i]     = __halves2bfloat162(h0, h1);
            ((__nv_bfloat162*)xh)[2 * i + 1] = __halves2bfloat162(h2, h3);
            ((__nv_bfloat162*)xl)[2 * i]     = __halves2bfloat162(l0, l1);
            ((__nv_bfloat162*)xl)[2 * i + 1] = __halves2bfloat162(l2, l3);
        }
    } else if (b < 5888) {
        const bool w1 = (b < 5632);
        const int K = w1 ? 768 : 512, Nn = w1 ? 512 : 128;
        const float* W = w1 ? W1 : W2;
        __nv_bfloat16* hi = w1 ? g_w1h : g_w2h;
        __nv_bfloat16* lo = w1 ? g_w1l : g_w2l;
        int idx = (b - (w1 ? 4096 : 5632)) * 256 + tid;
        if (idx < Nn * K) {
            int n = idx / K, k = idx - n * K;
            float v = W[(size_t)k * Nn + n];
            __nv_bfloat16 h = __float2bfloat16(v);
            hi[idx] = h;
            lo[idx] = __float2bfloat16(v - __bfloat162float(h));
        }
    } else {
        const int g = b - 5888;
        if (g == 0 && tid == 0) *loss = 0.f;
        __shared__ int cnt[NPG + 1];
        __shared__ int cur[NPG];
        __shared__ unsigned short sd[NE];
        for (int i = tid; i <= NPG; i += blockDim.x) cnt[i] = 0;
        __syncthreads();
        for (int e = tid; e < NE; e += blockDim.x) {
            int d = (e < EPG) ? (ed[g * EPG + e] - g * NPG) : (e - EPG);
            sd[e] = (unsigned short)d;
            atomicAdd(&cnt[d], 1);
        }
        __syncthreads();
        if (tid == 0) {
            int run = 0;
            for (int i = 0; i < NPG; i++) {
                int c = cnt[i]; cnt[i] = run;
                g_csro[g * (NPG + 1) + i] = run;
                run += c;
            }
            g_csro[g * (NPG + 1) + NPG] = run;
        }
        __syncthreads();
        for (int i = tid; i < NPG; i += blockDim.x) cur[i] = cnt[i];
        __syncthreads();
        for (int e = tid; e < NE; e += blockDim.x) {
            int s = (e < EPG) ? (es[g * EPG + e] - g * NPG) : (e - EPG);
            int p = atomicAdd(&cur[sd[e]], 1);
            g_csr[(size_t)g * NE + p] = (unsigned short)s;
        }
    }
}

// ============================ HMMA split-bf16 GEMM ============================
__device__ __forceinline__ void ldsm4(uint32_t addr, uint32_t& r0, uint32_t& r1,
                                      uint32_t& r2, uint32_t& r3) {
    asm volatile("ldmatrix.sync.aligned.m8n8.x4.shared.b16 {%0,%1,%2,%3}, [%4];"
                 : "=r"(r0), "=r"(r1), "=r"(r2), "=r"(r3) : "r"(addr));
}

// C[M x Nn] = A[M x K] * B[Nn x K]^T via interleaved passes:
//   merged phase (chunks 0..2nk-1): per k, (Ahi_k*Bhi_k) then (Ahi_k*Blo_k),
//     A loaded once per pair (A-ring reuse);
//   lo phase (chunks 2nk..3nk-1): Alo_k*Bhi_k.
// Separate 3-buffer A ring + 3-buffer B ring (96KB total), 2 CTA/SM,
// single barrier per chunk, prefetch overlapped with MMAs, ldmatrix.x4, SW128.
__global__ void __launch_bounds__(256, 2)
gemm_hmma(const __nv_bfloat16* __restrict__ Ahi, const __nv_bfloat16* __restrict__ Alo,
          const __nv_bfloat16* __restrict__ Bhi, const __nv_bfloat16* __restrict__ Blo,
          float* __restrict__ C, int Nn, int K) {
    constexpr int ATILE = 128 * 128;   // 16384 bytes per operand tile
    extern __shared__ char smb[];
    uint32_t sb;
    asm("{ .reg .u64 tt; cvta.to.shared.u64 tt, %1; cvt.u32.u64 %0, tt; }"
        : "=r"(sb) : "l"(smb));
    const int tid = threadIdx.x, lane = tid & 31, wid = tid >> 5;
    const int g = lane >> 2, t = lane & 3;
    const int bm = blockIdx.y * 128, bn = blockIdx.x * 128;
    const int wm = (wid >> 1) * 32, wn = (wid & 1) * 64;
    const int nk = K >> 6, nch = 3 * nk;
    const uint32_t bbase = sb + 3 * ATILE;
    const int aoff = ((lane & 7) + ((lane >> 3) & 1) * 8) * 128 + (lane >> 4) * 16;
    const int boff = ((lane & 7) + ((lane >> 4) & 1) * 8) * 128 + ((lane >> 3) & 1) * 16;

    float acc[2][8][4];
#pragma unroll
    for (int mf = 0; mf < 2; mf++)
#pragma unroll
        for (int nf = 0; nf < 8; nf++)
#pragma unroll
            for (int j = 0; j < 4; j++) acc[mf][nf][j] = 0.f;

    // A-ring slot for chunk c (3 slots)
    auto aslot = [&](int c) -> int {
        return (c < 2 * nk) ? ((c >> 1) % 3) : ((nk + c - 2 * nk) % 3);
    };

    auto prefetch = [&](int c) {
        const bool merged = (c < 2 * nk);
        const int k = merged ? (c >> 1) : (c - 2 * nk);
        const int kk = k << 6;
        const bool loadA = !merged || ((c & 1) == 0);
        const __nv_bfloat16* Bs = (merged && (c & 1)) ? Blo : Bhi;
        if (loadA) {
            const __nv_bfloat16* As = merged ? Ahi : Alo;
            uint32_t ast = sb + aslot(c) * ATILE;
            const __nv_bfloat16* Ag = As + (size_t)bm * K + kk;
#pragma unroll
            for (int u = 0; u < 4; u++) {
                int v = u * 256 + tid;
                int r = v >> 3, c16 = v & 7;
                asm volatile("cp.async.cg.shared.global [%0], [%1], 16;"
                             :: "r"(ast + SWZB(r * 128 + c16 * 16)),
                                "l"(Ag + (size_t)r * K + c16 * 8) : "memory");
            }
        }
        {
            uint32_t bst = bbase + (c % 3) * ATILE;
            const __nv_bfloat16* Bg = Bs + (size_t)bn * K + kk;
#pragma unroll
            for (int u = 0; u < 4; u++) {
                int v = u * 256 + tid;
                int r = v >> 3, c16 = v & 7;
                asm volatile("cp.async.cg.shared.global [%0], [%1], 16;"
                             :: "r"(bst + SWZB(r * 128 + c16 * 16)),
                                "l"(Bg + (size_t)r * K + c16 * 8) : "memory");
            }
        }
        asm volatile("cp.async.commit_group;" ::: "memory");
    };

    prefetch(0);
    prefetch(1);
    for (int c = 0; c < nch; c++) {
        if (c == nch - 1)
            asm volatile("cp.async.wait_group 0;" ::: "memory");
        else
            asm volatile("cp.async.wait_group 1;" ::: "memory");
        __syncthreads();
        if (c + 2 < nch) prefetch(c + 2);   // overlaps with MMAs below
        const uint32_t ab = sb + aslot(c) * ATILE;
        const uint32_t bb = bbase + (c % 3) * ATILE;
#pragma unroll
        for (int ks = 0; ks < 4; ks++) {
            uint32_t af[2][4], bf[8][2];
#pragma unroll
            for (int mf = 0; mf < 2; mf++)
                ldsm4(ab + SWZB((wm + mf * 16) * 128 + ks * 32 + aoff),
                      af[mf][0], af[mf][1], af[mf][2], af[mf][3]);
#pragma unroll
            for (int nf2 = 0; nf2 < 4; nf2++)
                ldsm4(bb + SWZB((wn + nf2 * 16) * 128 + ks * 32 + boff),
                      bf[2 * nf2][0], bf[2 * nf2][1], bf[2 * nf2 + 1][0], bf[2 * nf2 + 1][1]);
#pragma unroll
            for (int mf = 0; mf < 2; mf++)
#pragma unroll
                for (int nf = 0; nf < 8; nf++) {
                    asm volatile(
                        "mma.sync.aligned.m16n8k16.row.col.f32.bf16.bf16.f32 "
                        "{%0,%1,%2,%3}, {%4,%5,%6,%7}, {%8,%9}, {%0,%1,%2,%3};"
                        : "+f"(acc[mf][nf][0]), "+f"(acc[mf][nf][1]),
                          "+f"(acc[mf][nf][2]), "+f"(acc[mf][nf][3])
                        : "r"(af[mf][0]), "r"(af[mf][1]), "r"(af[mf][2]), "r"(af[mf][3]),
                          "r"(bf[nf][0]), "r"(bf[nf][1]));
                }
        }
    }

#pragma unroll
    for (int mf = 0; mf < 2; mf++)
#pragma unroll
        for (int nf = 0; nf < 8; nf++) {
            int row = bm + wm + mf * 16 + g;
            int col = bn + wn + nf * 8 + t * 2;
            *(float2*)&C[(size_t)row * Nn + col] =
                make_float2(acc[mf][nf][0], acc[mf][nf][1]);
            *(float2*)&C[(size_t)(row + 8) * Nn + col] =
                make_float2(acc[mf][nf][2], acc[mf][nf][3]);
        }
}

// ====== fused GAT: dots + softmax + aggregate (+optional cluster softmax) ======
__global__ void gat_agg(const float* __restrict__ h, const float* __restrict__ a_s,
                        const float* __restrict__ a_d, const float* __restrict__ bias,
                        float* __restrict__ outf, __nv_bfloat16* __restrict__ outh,
                        __nv_bfloat16* __restrict__ outl,
                        const float* __restrict__ Wc, const float* __restrict__ bc,
                        float* __restrict__ S, int H, int stride) {
    extern __shared__ float smem[];
    float* hb  = smem;                       // NPG*CH
    float* asr = hb + NPG * CH;
    float* adr = asr + NPG;
    int* soff  = (int*)(adr + NPG);
    unsigned short* ssrc = (unsigned short*)(soff + NPG + 1);

    const int g = blockIdx.x, hd = blockIdx.y;
    const int tid = threadIdx.x, wid = tid >> 5, lane = tid & 31;
    const int base = g * NPG;

    for (int i = tid; i < NPG * (CH / 4); i += blockDim.x) {
        int r = i / (CH / 4), c4 = (i % (CH / 4)) * 4;
        *(float4*)&hb[r * CH + c4] =
            *(const float4*)(h + (size_t)(base + r) * stride + hd * CH + c4);
    }
    for (int i = tid; i <= NPG; i += blockDim.x) soff[i] = g_csro[g * (NPG + 1) + i];
    for (int i = tid; i < NE / 2; i += blockDim.x)
        ((uint32_t*)ssrc)[i] = ((const uint32_t*)(g_csr + (size_t)g * NE))[i];
    __syncthreads();

    {
        float4 s4 = *(const float4*)(a_s + hd * CH + lane * 4);
        float4 d4 = *(const float4*)(a_d + hd * CH + lane * 4);
        for (int r = wid; r < NPG; r += 8) {
            float4 v = *(float4*)&hb[r * CH + lane * 4];
            float ps = v.x * s4.x + v.y * s4.y + v.z * s4.z + v.w * s4.w;
            float pd = v.x * d4.x + v.y * d4.y + v.z * d4.z + v.w * d4.w;
#pragma unroll
            for (int o = 16; o; o >>= 1) {
                ps += __shfl_xor_sync(0xffffffffu, ps, o);
                pd += __shfl_xor_sync(0xffffffffu, pd, o);
            }
            if (lane == 0) { asr[r] = ps; adr[r] = pd; }
        }
    }
    __syncthreads();

    float2 w01[4];
    if (S) {
#pragma unroll
        for (int j = 0; j < 4; j++)
            w01[j] = *(const float2*)(Wc + (lane * 4 + j) * 2);
    }
    float bc0 = S ? bc[0] : 0.f, bc1 = S ? bc[1] : 0.f;

    for (int d = wid; d < NPG; d += 8) {
        const int j0 = soff[d], j1 = soff[d + 1];
        const float add = adr[d];
        float m = -1e30f;
        for (int j = j0; j < j1; j++) {
            float l = asr[ssrc[j]] + add;
            l = l > 0.f ? l : 0.2f * l;
            m = fmaxf(m, l);
        }
        float sum = 0.f;
        float4 acc = make_float4(0.f, 0.f, 0.f, 0.f);
        for (int j = j0; j < j1; j++) {
            int s = ssrc[j];
            float l = asr[s] + add;
            l = l > 0.f ? l : 0.2f * l;
            float e = expf(l - m);
            sum += e;
            float4 hv = *(float4*)&hb[s * CH + lane * 4];
            acc.x += e * hv.x; acc.y += e * hv.y;
            acc.z += e * hv.z; acc.w += e * hv.w;
        }
        float inv = 1.f / (sum + 1e-16f);
        float4 b4 = *(const float4*)(bias + hd * CH + lane * 4);
        acc.x = fmaxf(acc.x * inv + b4.x, 0.f);
        acc.y = fmaxf(acc.y * inv + b4.y, 0.f);
        acc.z = fmaxf(acc.z * inv + b4.z, 0.f);
        acc.w = fmaxf(acc.w * inv + b4.w, 0.f);
        size_t o = (size_t)(base + d) * stride + hd * CH + lane * 4;
        if (outf) *(float4*)(outf + o) = acc;
        if (outh) {
            __nv_bfloat16 h0 = __float2bfloat16(acc.x), h1 = __float2bfloat16(acc.y);
            __nv_bfloat16 h2 = __float2bfloat16(acc.z), h3 = __float2bfloat16(acc.w);
            *(__nv_bfloat162*)(outh + o)     = __halves2bfloat162(h0, h1);
            *(__nv_bfloat162*)(outh + o + 2) = __halves2bfloat162(h2, h3);
            __nv_bfloat16 l0 = __float2bfloat16(acc.x - __bfloat162float(h0));
            __nv_bfloat16 l1 = __float2bfloat16(acc.y - __bfloat162float(h1));
            __nv_bfloat16 l2 = __float2bfloat16(acc.z - __bfloat162float(h2));
            __nv_bfloat16 l3 = __float2bfloat16(acc.w - __bfloat162float(h3));
            *(__nv_bfloat162*)(outl + o)     = __halves2bfloat162(l0, l1);
            *(__nv_bfloat162*)(outl + o + 2) = __halves2bfloat162(l2, l3);
        }
        if (S) {
            float p0 = acc.x * w01[0].x + acc.y * w01[1].x + acc.z * w01[2].x + acc.w * w01[3].x;
            float p1 = acc.x * w01[0].y + acc.y * w01[1].y + acc.z * w01[2].y + acc.w * w01[3].y;
#pragma unroll
            for (int o2_ = 16; o2_; o2_ >>= 1) {
                p0 += __shfl_xor_sync(0xffffffffu, p0, o2_);
                p1 += __shfl_xor_sync(0xffffffffu, p1, o2_);
            }
            if (lane == 0) {
                float z0 = p0 + bc0, z1 = p1 + bc1;
                float mm = fmaxf(z0, z1);
                float e0 = expf(z0 - mm), e1 = expf(z1 - mm);
                float is = 1.f / (e0 + e1);
                S[(base + d) * 2] = e0 * is;
                S[(base + d) * 2 + 1] = e1 * is;
            }
        }
    }
}

// ============== merged head: aggregate loss + per-graph readout MLP ==============
__global__ void head_k(const float* __restrict__ S, const int* __restrict__ es,
                       const int* __restrict__ ed, const float* __restrict__ h2,
                       const float* __restrict__ Wf1, const float* __restrict__ bf1,
                       const float* __restrict__ Wf2, const float* __restrict__ bf2,
                       float* __restrict__ out, float* __restrict__ loss) {
    const int g = blockIdx.x, tid = threadIdx.x;   // 256 threads
    __shared__ float s0[NPG];
    __shared__ float sub[CH];
    __shared__ float hid[CH];
    __shared__ float sa[4];

    float a00 = 0.f, a01 = 0.f, a10 = 0.f, a11 = 0.f;
    for (int e = tid; e < EPG; e += blockDim.x) {
        int so = es[g * EPG + e], dn = ed[g * EPG + e];
        float ss0 = S[so * 2], ss1 = S[so * 2 + 1];
        float d0 = S[dn * 2], d1 = S[dn * 2 + 1];
        a00 += ss0 * d0; a01 += ss0 * d1; a10 += ss1 * d0; a11 += ss1 * d1;
    }
#pragma unroll
    for (int o = 16; o; o >>= 1) {
        a00 += __shfl_xor_sync(0xffffffffu, a00, o);
        a01 += __shfl_xor_sync(0xffffffffu, a01, o);
        a10 += __shfl_xor_sync(0xffffffffu, a10, o);
        a11 += __shfl_xor_sync(0xffffffffu, a11, o);
    }
    if (tid < 4) sa[tid] = 0.f;
    for (int i = tid; i < NPG; i += blockDim.x) s0[i] = S[(g * NPG + i) * 2];
    __syncthreads();
    if ((tid & 31) == 0) {
        atomicAdd(&sa[0], a00); atomicAdd(&sa[1], a01);
        atomicAdd(&sa[2], a10); atomicAdd(&sa[3], a11);
    }
    __syncthreads();
    if (tid == 0) {
        float r0 = fmaxf(fabsf(sa[0]) + fabsf(sa[1]), 1e-5f);
        float r1 = fmaxf(fabsf(sa[2]) + fabsf(sa[3]), 1e-5f);
        float d0 = sa[0] / r0 - 1.f, d1 = sa[3] / r1 - 1.f;
        float lg = 0.5f * (d0 * d0 + d1 * d1);
        atomicAdd(loss, lg * (1.f / (float)GG));
    }

    if (tid < CH) {
        float acc = 0.f;
        for (int n = 0; n < NPG; n++)
            acc += s0[n] * h2[(size_t)(g * NPG + n) * CH + tid];
        sub[tid] = acc;
    }
    __syncthreads();
    if (tid < CH) {
        float hh = bf1[tid];
        for (int c = 0; c < CH; c++) hh += sub[c] * Wf1[c * CH + tid];
        hid[tid] = fmaxf(hh, 0.f);
    }
    __syncthreads();
    int w = tid >> 5, lane = tid & 31;
    if (w < 2) {
        float p = 0.f;
        for (int j = lane; j < CH; j += 32) p += hid[j] * Wf2[j * 2 + w];
#pragma unroll
        for (int o = 16; o; o >>= 1) p += __shfl_down_sync(0xffffffffu, p, o);
        if (lane == 0) out[g * 2 + w] = p + bf2[w];
    }
}

// ============================ launcher ============================
extern "C" void kernel_launch(void* const* d_in, const int* in_sizes, int n_in,
                              void* d_out, int out_size) {
    const float* x   = (const float*)d_in[0];
    const int*   ei  = (const int*)d_in[1];
    const float* W1  = (const float*)d_in[3];
    const float* as1 = (const float*)d_in[4];
    const float* ad1 = (const float*)d_in[5];
    const float* b1  = (const float*)d_in[6];
    const float* W2  = (const float*)d_in[7];
    const float* as2 = (const float*)d_in[8];
    const float* ad2 = (const float*)d_in[9];
    const float* b2  = (const float*)d_in[10];
    const float* Wc  = (const float*)d_in[11];
    const float* bc  = (const float*)d_in[12];
    const float* Wf1 = (const float*)d_in[13];
    const float* bf1 = (const float*)d_in[14];
    const float* Wf2 = (const float*)d_in[15];
    const float* bf2 = (const float*)d_in[16];
    const int* es = ei;
    const int* ed = ei + EE;
    float* out = (float*)d_out;

    float *h1, *h2, *o2, *S;
    __nv_bfloat16 *xh, *xl, *o1h, *o1l, *w1h, *w1l, *w2h, *w2l;
    cudaGetSymbolAddress((void**)&h1, g_h1);
    cudaGetSymbolAddress((void**)&h2, g_h2);
    cudaGetSymbolAddress((void**)&o2, g_o2);
    cudaGetSymbolAddress((void**)&xh, g_xh);
    cudaGetSymbolAddress((void**)&xl, g_xl);
    cudaGetSymbolAddress((void**)&o1h, g_o1h);
    cudaGetSymbolAddress((void**)&o1l, g_o1l);
    cudaGetSymbolAddress((void**)&w1h, g_w1h);
    cudaGetSymbolAddress((void**)&w1l, g_w1l);
    cudaGetSymbolAddress((void**)&w2h, g_w2h);
    cudaGetSymbolAddress((void**)&w2l, g_w2l);
    cudaGetSymbolAddress((void**)&S, g_S);

    const int GAT_SMEM = NPG * CH * 4 + 2 * NPG * 4 + (NPG + 1) * 4 + NE * 2;
    const int GEMM_SMEM = 6 * 128 * 128;   // 3 A bufs + 3 B bufs = 98304
    cudaFuncSetAttribute(gat_agg, cudaFuncAttributeMaxDynamicSharedMemorySize, GAT_SMEM);
    cudaFuncSetAttribute(gemm_hmma, cudaFuncAttributeMaxDynamicSharedMemorySize, GEMM_SMEM);

    // fused prep (x split + W splits + CSR + loss zero)
    prep<<<6144, 256>>>(x, xh, xl, W1, W2, es, ed, out + (out_size - 1));

    // layer 1: [NN,768] x [768,512]
    gemm_hmma<<<dim3(4, 400), 256, GEMM_SMEM>>>(xh, xl, w1h, w1l, h1, 512, 768);
    gat_agg<<<dim3(GG, 4), 256, GAT_SMEM>>>(h1, as1, ad1, b1,
                                            nullptr, o1h, o1l,
                                            nullptr, nullptr, nullptr, 4, 512);
    // layer 2: [NN,512] x [512,128]
    gemm_hmma<<<dim3(1, 400), 256, GEMM_SMEM>>>(o1h, o1l, w2h, w2l, h2, 128, 512);
    gat_agg<<<dim3(GG, 1), 256, GAT_SMEM>>>(h2, as2, ad2, b2,
                                            o2, nullptr, nullptr,
                                            Wc, bc, S, 1, 128);
    // merged head
    head_k<<<GG, 256>>>(S, es, ed, o2, Wf1, bf1, Wf2, bf2, out, out + (out_size - 1));
}

// round 16
// speedup vs baseline: 1.0658x; 1.0090x over previous
#include <cuda_runtime.h>
#include <cuda_bf16.h>
#include <math.h>
#include <stdint.h>

#define NN   51200
#define GG   256
#define NPG  200
#define EE   409600
#define EPG  1600
#define CH   128
#define NE   (EPG + NPG)   // edges per graph incl self-loops = 1800

// ---------------- scratch (device globals; no allocs allowed) ----------------
__device__ float g_h1[(size_t)NN * 512];
__device__ float g_h2[(size_t)NN * CH];
__device__ float g_o2[(size_t)NN * CH];
__device__ __nv_bfloat16 g_xh[(size_t)NN * 768];
__device__ __nv_bfloat16 g_xl[(size_t)NN * 768];
__device__ __nv_bfloat16 g_o1h[(size_t)NN * 512];
__device__ __nv_bfloat16 g_o1l[(size_t)NN * 512];
__device__ __nv_bfloat16 g_w1h[512 * 768];
__device__ __nv_bfloat16 g_w1l[512 * 768];
__device__ __nv_bfloat16 g_w2h[128 * 512];
__device__ __nv_bfloat16 g_w2l[128 * 512];
__device__ float g_S[NN * 2];
__device__ unsigned short g_csr[(size_t)GG * NE];
__device__ int g_csro[GG * (NPG + 1)];

#define SWZB(o) ((o) ^ (((o) >> 3) & 0x70))

// =============== fused prep: x split + W1/W2 split + CSR + loss init ===============
__global__ void prep(const float* __restrict__ x, __nv_bfloat16* __restrict__ xh,
                     __nv_bfloat16* __restrict__ xl,
                     const float* __restrict__ W1, const float* __restrict__ W2,
                     const int* __restrict__ es, const int* __restrict__ ed,
                     float* __restrict__ loss) {
    const int b = blockIdx.x, tid = threadIdx.x;
    if (b < 4096) {
        const size_t n4 = (size_t)NN * 768 / 4;
        size_t i = (size_t)b * 256 + tid;
        const size_t stride = 4096 * 256;
        for (; i < n4; i += stride) {
            float4 v = ((const float4*)x)[i];
            __nv_bfloat16 h0 = __float2bfloat16(v.x), h1 = __float2bfloat16(v.y);
            __nv_bfloat16 h2 = __float2bfloat16(v.z), h3 = __float2bfloat16(v.w);
            __nv_bfloat16 l0 = __float2bfloat16(v.x - __bfloat162float(h0));
            __nv_bfloat16 l1 = __float2bfloat16(v.y - __bfloat162float(h1));
            __nv_bfloat16 l2 = __float2bfloat16(v.z - __bfloat162float(h2));
            __nv_bfloat16 l3 = __float2bfloat16(v.w - __bfloat162float(h3));
            ((__nv_bfloat162*)xh)[2 * i]     = __halves2bfloat162(h0, h1);
            ((__nv_bfloat162*)xh)[2 * i + 1] = __halves2bfloat162(h2, h3);
            ((__nv_bfloat162*)xl)[2 * i]     = __halves2bfloat162(l0, l1);
            ((__nv_bfloat162*)xl)[2 * i + 1] = __halves2bfloat162(l2, l3);
        }
    } else if (b < 5888) {
        const bool w1 = (b < 5632);
        const int K = w1 ? 768 : 512, Nn = w1 ? 512 : 128;
        const float* W = w1 ? W1 : W2;
        __nv_bfloat16* hi = w1 ? g_w1h : g_w2h;
        __nv_bfloat16* lo = w1 ? g_w1l : g_w2l;
        int idx = (b - (w1 ? 4096 : 5632)) * 256 + tid;
        if (idx < Nn * K) {
            int n = idx / K, k = idx - n * K;
            float v = W[(size_t)k * Nn + n];
            __nv_bfloat16 h = __float2bfloat16(v);
            hi[idx] = h;
            lo[idx] = __float2bfloat16(v - __bfloat162float(h));
        }
    } else {
        const int g = b - 5888;
        if (g == 0 && tid == 0) *loss = 0.f;
        __shared__ int cnt[NPG + 1];
        __shared__ int cur[NPG];
        __shared__ unsigned short sd[NE];
        for (int i = tid; i <= NPG; i += blockDim.x) cnt[i] = 0;
        __syncthreads();
        for (int e = tid; e < NE; e += blockDim.x) {
            int d = (e < EPG) ? (ed[g * EPG + e] - g * NPG) : (e - EPG);
            sd[e] = (unsigned short)d;
            atomicAdd(&cnt[d], 1);
        }
        __syncthreads();
        if (tid == 0) {
            int run = 0;
            for (int i = 0; i < NPG; i++) {
                int c = cnt[i]; cnt[i] = run;
                g_csro[g * (NPG + 1) + i] = run;
                run += c;
            }
            g_csro[g * (NPG + 1) + NPG] = run;
        }
        __syncthreads();
        for (int i = tid; i < NPG; i += blockDim.x) cur[i] = cnt[i];
        __syncthreads();
        for (int e = tid; e < NE; e += blockDim.x) {
            int s = (e < EPG) ? (es[g * EPG + e] - g * NPG) : (e - EPG);
            int p = atomicAdd(&cur[sd[e]], 1);
            g_csr[(size_t)g * NE + p] = (unsigned short)s;
        }
    }
}

// ============================ HMMA split-bf16 GEMM ============================
__device__ __forceinline__ void ldsm4(uint32_t addr, uint32_t& r0, uint32_t& r1,
                                      uint32_t& r2, uint32_t& r3) {
    asm volatile("ldmatrix.sync.aligned.m8n8.x4.shared.b16 {%0,%1,%2,%3}, [%4];"
                 : "=r"(r0), "=r"(r1), "=r"(r2), "=r"(r3) : "r"(addr));
}

// C[M x Nn] = A[M x K] * B[Nn x K]^T via merged-pair iterations:
//   it < nk : stage {Ahi_k, Bhi_k, Blo_k}; compute Ahi*Bhi and Ahi*Blo from
//             ONE A-fragment load (2x MMA density per barrier pair);
//   it >= nk: stage {Alo_k, Bhi_k}; compute Alo*Bhi.
// A ring = 2 x 16KB, B ring = 4 x 16KB (96KB total -> 2 CTA/SM).
// Per iteration: wait_group(1|0) + sync, compute, sync, prefetch(it+2).
__global__ void __launch_bounds__(256, 2)
gemm_hmma(const __nv_bfloat16* __restrict__ Ahi, const __nv_bfloat16* __restrict__ Alo,
          const __nv_bfloat16* __restrict__ Bhi, const __nv_bfloat16* __restrict__ Blo,
          float* __restrict__ C, int Nn, int K) {
    constexpr int ATILE = 128 * 128;   // 16384 bytes per operand tile
    extern __shared__ char smb[];
    uint32_t sb;
    asm("{ .reg .u64 tt; cvta.to.shared.u64 tt, %1; cvt.u32.u64 %0, tt; }"
        : "=r"(sb) : "l"(smb));
    const int tid = threadIdx.x, lane = tid & 31, wid = tid >> 5;
    const int g = lane >> 2, t = lane & 3;
    const int bm = blockIdx.y * 128, bn = blockIdx.x * 128;
    const int wm = (wid >> 1) * 32, wn = (wid & 1) * 64;
    const int nk = K >> 6, nit = 2 * nk;
    const uint32_t bbase = sb + 2 * ATILE;       // B ring after 2 A slots
    const int aoff = ((lane & 7) + ((lane >> 3) & 1) * 8) * 128 + (lane >> 4) * 16;
    const int boff = ((lane & 7) + ((lane >> 4) & 1) * 8) * 128 + ((lane >> 3) & 1) * 16;

    float acc[2][8][4];
#pragma unroll
    for (int mf = 0; mf < 2; mf++)
#pragma unroll
        for (int nf = 0; nf < 8; nf++)
#pragma unroll
            for (int j = 0; j < 4; j++) acc[mf][nf][j] = 0.f;

    auto prefetch = [&](int it) {
        const bool merged = (it < nk);
        const int k = merged ? it : it - nk;
        const int kk = k << 6;
        const uint32_t ast  = sb + (it & 1) * ATILE;
        const uint32_t b1st = bbase + 2 * (it & 1) * ATILE;
        const __nv_bfloat16* Ag = (merged ? Ahi : Alo) + (size_t)bm * K + kk;
        const __nv_bfloat16* B1 = Bhi + (size_t)bn * K + kk;
#pragma unroll
        for (int u = 0; u < 4; u++) {
            int v = u * 256 + tid;
            int r = v >> 3, c16 = v & 7;
            asm volatile("cp.async.cg.shared.global [%0], [%1], 16;"
                         :: "r"(ast + SWZB(r * 128 + c16 * 16)),
                            "l"(Ag + (size_t)r * K + c16 * 8) : "memory");
        }
#pragma unroll
        for (int u = 0; u < 4; u++) {
            int v = u * 256 + tid;
            int r = v >> 3, c16 = v & 7;
            asm volatile("cp.async.cg.shared.global [%0], [%1], 16;"
                         :: "r"(b1st + SWZB(r * 128 + c16 * 16)),
                            "l"(B1 + (size_t)r * K + c16 * 8) : "memory");
        }
        if (merged) {
            const __nv_bfloat16* B2 = Blo + (size_t)bn * K + kk;
            const uint32_t b2st = b1st + ATILE;
#pragma unroll
            for (int u = 0; u < 4; u++) {
                int v = u * 256 + tid;
                int r = v >> 3, c16 = v & 7;
                asm volatile("cp.async.cg.shared.global [%0], [%1], 16;"
                             :: "r"(b2st + SWZB(r * 128 + c16 * 16)),
                                "l"(B2 + (size_t)r * K + c16 * 8) : "memory");
            }
        }
        asm volatile("cp.async.commit_group;" ::: "memory");
    };

    prefetch(0);
    prefetch(1);
    for (int it = 0; it < nit; it++) {
        if (it == nit - 1)
            asm volatile("cp.async.wait_group 0;" ::: "memory");
        else
            asm volatile("cp.async.wait_group 1;" ::: "memory");
        __syncthreads();
        const bool merged = (it < nk);
        const uint32_t ab = sb + (it & 1) * ATILE;
        const uint32_t bb = bbase + 2 * (it & 1) * ATILE;
#pragma unroll
        for (int ks = 0; ks < 4; ks++) {
            uint32_t af[2][4], bf[8][2];
#pragma unroll
            for (int mf = 0; mf < 2; mf++)
                ldsm4(ab + SWZB((wm + mf * 16) * 128 + ks * 32 + aoff),
                      af[mf][0], af[mf][1], af[mf][2], af[mf][3]);
#pragma unroll
            for (int nf2 = 0; nf2 < 4; nf2++)
                ldsm4(bb + SWZB((wn + nf2 * 16) * 128 + ks * 32 + boff),
                      bf[2 * nf2][0], bf[2 * nf2][1], bf[2 * nf2 + 1][0], bf[2 * nf2 + 1][1]);
#pragma unroll
            for (int mf = 0; mf < 2; mf++)
#pragma unroll
                for (int nf = 0; nf < 8; nf++) {
                    asm volatile(
                        "mma.sync.aligned.m16n8k16.row.col.f32.bf16.bf16.f32 "
                        "{%0,%1,%2,%3}, {%4,%5,%6,%7}, {%8,%9}, {%0,%1,%2,%3};"
                        : "+f"(acc[mf][nf][0]), "+f"(acc[mf][nf][1]),
                          "+f"(acc[mf][nf][2]), "+f"(acc[mf][nf][3])
                        : "r"(af[mf][0]), "r"(af[mf][1]), "r"(af[mf][2]), "r"(af[mf][3]),
                          "r"(bf[nf][0]), "r"(bf[nf][1]));
                }
            if (merged) {    // second B variant against SAME A fragments
#pragma unroll
                for (int nf2 = 0; nf2 < 4; nf2++)
                    ldsm4(bb + ATILE + SWZB((wn + nf2 * 16) * 128 + ks * 32 + boff),
                          bf[2 * nf2][0], bf[2 * nf2][1], bf[2 * nf2 + 1][0], bf[2 * nf2 + 1][1]);
#pragma unroll
                for (int mf = 0; mf < 2; mf++)
#pragma unroll
                    for (int nf = 0; nf < 8; nf++) {
                        asm volatile(
                            "mma.sync.aligned.m16n8k16.row.col.f32.bf16.bf16.f32 "
                            "{%0,%1,%2,%3}, {%4,%5,%6,%7}, {%8,%9}, {%0,%1,%2,%3};"
                            : "+f"(acc[mf][nf][0]), "+f"(acc[mf][nf][1]),
                              "+f"(acc[mf][nf][2]), "+f"(acc[mf][nf][3])
                            : "r"(af[mf][0]), "r"(af[mf][1]), "r"(af[mf][2]), "r"(af[mf][3]),
                              "r"(bf[nf][0]), "r"(bf[nf][1]));
                    }
            }
        }
        __syncthreads();                 // all warps done reading slots of 'it'
        if (it + 2 < nit) prefetch(it + 2);   // overwrites slots of 'it'; overlaps compute of it+1
    }

#pragma unroll
    for (int mf = 0; mf < 2; mf++)
#pragma unroll
        for (int nf = 0; nf < 8; nf++) {
            int row = bm + wm + mf * 16 + g;
            int col = bn + wn + nf * 8 + t * 2;
            *(float2*)&C[(size_t)row * Nn + col] =
                make_float2(acc[mf][nf][0], acc[mf][nf][1]);
            *(float2*)&C[(size_t)(row + 8) * Nn + col] =
                make_float2(acc[mf][nf][2], acc[mf][nf][3]);
        }
}

// ====== fused GAT: dots + softmax + aggregate (+optional cluster softmax) ======
__global__ void gat_agg(const float* __restrict__ h, const float* __restrict__ a_s,
                        const float* __restrict__ a_d, const float* __restrict__ bias,
                        float* __restrict__ outf, __nv_bfloat16* __restrict__ outh,
                        __nv_bfloat16* __restrict__ outl,
                        const float* __restrict__ Wc, const float* __restrict__ bc,
                        float* __restrict__ S, int H, int stride) {
    extern __shared__ float smem[];
    float* hb  = smem;                       // NPG*CH
    float* asr = hb + NPG * CH;
    float* adr = asr + NPG;
    int* soff  = (int*)(adr + NPG);
    unsigned short* ssrc = (unsigned short*)(soff + NPG + 1);

    const int g = blockIdx.x, hd = blockIdx.y;
    const int tid = threadIdx.x, wid = tid >> 5, lane = tid & 31;
    const int base = g * NPG;

    for (int i = tid; i < NPG * (CH / 4); i += blockDim.x) {
        int r = i / (CH / 4), c4 = (i % (CH / 4)) * 4;
        *(float4*)&hb[r * CH + c4] =
            *(const float4*)(h + (size_t)(base + r) * stride + hd * CH + c4);
    }
    for (int i = tid; i <= NPG; i += blockDim.x) soff[i] = g_csro[g * (NPG + 1) + i];
    for (int i = tid; i < NE / 2; i += blockDim.x)
        ((uint32_t*)ssrc)[i] = ((const uint32_t*)(g_csr + (size_t)g * NE))[i];
    __syncthreads();

    {
        float4 s4 = *(const float4*)(a_s + hd * CH + lane * 4);
        float4 d4 = *(const float4*)(a_d + hd * CH + lane * 4);
        for (int r = wid; r < NPG; r += 8) {
            float4 v = *(float4*)&hb[r * CH + lane * 4];
            float ps = v.x * s4.x + v.y * s4.y + v.z * s4.z + v.w * s4.w;
            float pd = v.x * d4.x + v.y * d4.y + v.z * d4.z + v.w * d4.w;
#pragma unroll
            for (int o = 16; o; o >>= 1) {
                ps += __shfl_xor_sync(0xffffffffu, ps, o);
                pd += __shfl_xor_sync(0xffffffffu, pd, o);
            }
            if (lane == 0) { asr[r] = ps; adr[r] = pd; }
        }
    }
    __syncthreads();

    float2 w01[4];
    if (S) {
#pragma unroll
        for (int j = 0; j < 4; j++)
            w01[j] = *(const float2*)(Wc + (lane * 4 + j) * 2);
    }
    float bc0 = S ? bc[0] : 0.f, bc1 = S ? bc[1] : 0.f;

    for (int d = wid; d < NPG; d += 8) {
        const int j0 = soff[d], j1 = soff[d + 1];
        const float add = adr[d];
        float m = -1e30f;
        for (int j = j0; j < j1; j++) {
            float l = asr[ssrc[j]] + add;
            l = l > 0.f ? l : 0.2f * l;
            m = fmaxf(m, l);
        }
        float sum = 0.f;
        float4 acc = make_float4(0.f, 0.f, 0.f, 0.f);
        for (int j = j0; j < j1; j++) {
            int s = ssrc[j];
            float l = asr[s] + add;
            l = l > 0.f ? l : 0.2f * l;
            float e = expf(l - m);
            sum += e;
            float4 hv = *(float4*)&hb[s * CH + lane * 4];
            acc.x += e * hv.x; acc.y += e * hv.y;
            acc.z += e * hv.z; acc.w += e * hv.w;
        }
        float inv = 1.f / (sum + 1e-16f);
        float4 b4 = *(const float4*)(bias + hd * CH + lane * 4);
        acc.x = fmaxf(acc.x * inv + b4.x, 0.f);
        acc.y = fmaxf(acc.y * inv + b4.y, 0.f);
        acc.z = fmaxf(acc.z * inv + b4.z, 0.f);
        acc.w = fmaxf(acc.w * inv + b4.w, 0.f);
        size_t o = (size_t)(base + d) * stride + hd * CH + lane * 4;
        if (outf) *(float4*)(outf + o) = acc;
        if (outh) {
            __nv_bfloat16 h0 = __float2bfloat16(acc.x), h1 = __float2bfloat16(acc.y);
            __nv_bfloat16 h2 = __float2bfloat16(acc.z), h3 = __float2bfloat16(acc.w);
            *(__nv_bfloat162*)(outh + o)     = __halves2bfloat162(h0, h1);
            *(__nv_bfloat162*)(outh + o + 2) = __halves2bfloat162(h2, h3);
            __nv_bfloat16 l0 = __float2bfloat16(acc.x - __bfloat162float(h0));
            __nv_bfloat16 l1 = __float2bfloat16(acc.y - __bfloat162float(h1));
            __nv_bfloat16 l2 = __float2bfloat16(acc.z - __bfloat162float(h2));
            __nv_bfloat16 l3 = __float2bfloat16(acc.w - __bfloat162float(h3));
            *(__nv_bfloat162*)(outl + o)     = __halves2bfloat162(l0, l1);
            *(__nv_bfloat162*)(outl + o + 2) = __halves2bfloat162(l2, l3);
        }
        if (S) {
            float p0 = acc.x * w01[0].x + acc.y * w01[1].x + acc.z * w01[2].x + acc.w * w01[3].x;
            float p1 = acc.x * w01[0].y + acc.y * w01[1].y + acc.z * w01[2].y + acc.w * w01[3].y;
#pragma unroll
            for (int o2_ = 16; o2_; o2_ >>= 1) {
                p0 += __shfl_xor_sync(0xffffffffu, p0, o2_);
                p1 += __shfl_xor_sync(0xffffffffu, p1, o2_);
            }
            if (lane == 0) {
                float z0 = p0 + bc0, z1 = p1 + bc1;
                float mm = fmaxf(z0, z1);
                float e0 = expf(z0 - mm), e1 = expf(z1 - mm);
                float is = 1.f / (e0 + e1);
                S[(base + d) * 2] = e0 * is;
                S[(base + d) * 2 + 1] = e1 * is;
            }
        }
    }
}

// ============== merged head: aggregate loss + per-graph readout MLP ==============
__global__ void head_k(const float* __restrict__ S, const int* __restrict__ es,
                       const int* __restrict__ ed, const float* __restrict__ h2,
                       const float* __restrict__ Wf1, const float* __restrict__ bf1,
                       const float* __restrict__ Wf2, const float* __restrict__ bf2,
                       float* __restrict__ out, float* __restrict__ loss) {
    const int g = blockIdx.x, tid = threadIdx.x;   // 256 threads
    __shared__ float s0[NPG];
    __shared__ float sub[CH];
    __shared__ float hid[CH];
    __shared__ float sa[4];

    float a00 = 0.f, a01 = 0.f, a10 = 0.f, a11 = 0.f;
    for (int e = tid; e < EPG; e += blockDim.x) {
        int so = es[g * EPG + e], dn = ed[g * EPG + e];
        float ss0 = S[so * 2], ss1 = S[so * 2 + 1];
        float d0 = S[dn * 2], d1 = S[dn * 2 + 1];
        a00 += ss0 * d0; a01 += ss0 * d1; a10 += ss1 * d0; a11 += ss1 * d1;
    }
#pragma unroll
    for (int o = 16; o; o >>= 1) {
        a00 += __shfl_xor_sync(0xffffffffu, a00, o);
        a01 += __shfl_xor_sync(0xffffffffu, a01, o);
        a10 += __shfl_xor_sync(0xffffffffu, a10, o);
        a11 += __shfl_xor_sync(0xffffffffu, a11, o);
    }
    if (tid < 4) sa[tid] = 0.f;
    for (int i = tid; i < NPG; i += blockDim.x) s0[i] = S[(g * NPG + i) * 2];
    __syncthreads();
    if ((tid & 31) == 0) {
        atomicAdd(&sa[0], a00); atomicAdd(&sa[1], a01);
        atomicAdd(&sa[2], a10); atomicAdd(&sa[3], a11);
    }
    __syncthreads();
    if (tid == 0) {
        float r0 = fmaxf(fabsf(sa[0]) + fabsf(sa[1]), 1e-5f);
        float r1 = fmaxf(fabsf(sa[2]) + fabsf(sa[3]), 1e-5f);
        float d0 = sa[0] / r0 - 1.f, d1 = sa[3] / r1 - 1.f;
        float lg = 0.5f * (d0 * d0 + d1 * d1);
        atomicAdd(loss, lg * (1.f / (float)GG));
    }

    if (tid < CH) {
        float acc = 0.f;
        for (int n = 0; n < NPG; n++)
            acc += s0[n] * h2[(size_t)(g * NPG + n) * CH + tid];
        sub[tid] = acc;
    }
    __syncthreads();
    if (tid < CH) {
        float hh = bf1[tid];
        for (int c = 0; c < CH; c++) hh += sub[c] * Wf1[c * CH + tid];
        hid[tid] = fmaxf(hh, 0.f);
    }
    __syncthreads();
    int w = tid >> 5, lane = tid & 31;
    if (w < 2) {
        float p = 0.f;
        for (int j = lane; j < CH; j += 32) p += hid[j] * Wf2[j * 2 + w];
#pragma unroll
        for (int o = 16; o; o >>= 1) p += __shfl_down_sync(0xffffffffu, p, o);
        if (lane == 0) out[g * 2 + w] = p + bf2[w];
    }
}

// ============================ launcher ============================
extern "C" void kernel_launch(void* const* d_in, const int* in_sizes, int n_in,
                              void* d_out, int out_size) {
    const float* x   = (const float*)d_in[0];
    const int*   ei  = (const int*)d_in[1];
    const float* W1  = (const float*)d_in[3];
    const float* as1 = (const float*)d_in[4];
    const float* ad1 = (const float*)d_in[5];
    const float* b1  = (const float*)d_in[6];
    const float* W2  = (const float*)d_in[7];
    const float* as2 = (const float*)d_in[8];
    const float* ad2 = (const float*)d_in[9];
    const float* b2  = (const float*)d_in[10];
    const float* Wc  = (const float*)d_in[11];
    const float* bc  = (const float*)d_in[12];
    const float* Wf1 = (const float*)d_in[13];
    const float* bf1 = (const float*)d_in[14];
    const float* Wf2 = (const float*)d_in[15];
    const float* bf2 = (const float*)d_in[16];
    const int* es = ei;
    const int* ed = ei + EE;
    float* out = (float*)d_out;

    float *h1, *h2, *o2, *S;
    __nv_bfloat16 *xh, *xl, *o1h, *o1l, *w1h, *w1l, *w2h, *w2l;
    cudaGetSymbolAddress((void**)&h1, g_h1);
    cudaGetSymbolAddress((void**)&h2, g_h2);
    cudaGetSymbolAddress((void**)&o2, g_o2);
    cudaGetSymbolAddress((void**)&xh, g_xh);
    cudaGetSymbolAddress((void**)&xl, g_xl);
    cudaGetSymbolAddress((void**)&o1h, g_o1h);
    cudaGetSymbolAddress((void**)&o1l, g_o1l);
    cudaGetSymbolAddress((void**)&w1h, g_w1h);
    cudaGetSymbolAddress((void**)&w1l, g_w1l);
    cudaGetSymbolAddress((void**)&w2h, g_w2h);
    cudaGetSymbolAddress((void**)&w2l, g_w2l);
    cudaGetSymbolAddress((void**)&S, g_S);

    const int GAT_SMEM = NPG * CH * 4 + 2 * NPG * 4 + (NPG + 1) * 4 + NE * 2;
    const int GEMM_SMEM = 6 * 128 * 128;   // 2 A bufs + 4 B bufs = 98304
    cudaFuncSetAttribute(gat_agg, cudaFuncAttributeMaxDynamicSharedMemorySize, GAT_SMEM);
    cudaFuncSetAttribute(gemm_hmma, cudaFuncAttributeMaxDynamicSharedMemorySize, GEMM_SMEM);

    // fused prep (x split + W splits + CSR + loss zero)
    prep<<<6144, 256>>>(x, xh, xl, W1, W2, es, ed, out + (out_size - 1));

    // layer 1: [NN,768] x [768,512]
    gemm_hmma<<<dim3(4, 400), 256, GEMM_SMEM>>>(xh, xl, w1h, w1l, h1, 512, 768);
    gat_agg<<<dim3(GG, 4), 256, GAT_SMEM>>>(h1, as1, ad1, b1,
                                            nullptr, o1h, o1l,
                                            nullptr, nullptr, nullptr, 4, 512);
    // layer 2: [NN,512] x [512,128]
    gemm_hmma<<<dim3(1, 400), 256, GEMM_SMEM>>>(o1h, o1l, w2h, w2l, h2, 128, 512);
    gat_agg<<<dim3(GG, 1), 256, GAT_SMEM>>>(h2, as2, ad2, b2,
                                            o2, nullptr, nullptr,
                                            Wc, bc, S, 1, 128);
    // merged head
    head_k<<<GG, 256>>>(S, es, ed, o2, Wf1, bf1, Wf2, bf2, out, out + (out_size - 1));
}

// round 17
// speedup vs baseline: 1.1754x; 1.1028x over previous
#include <cuda_runtime.h>
#include <cuda_bf16.h>
#include <math.h>
#include <stdint.h>

#define NN   51200
#define GG   256
#define NPG  200
#define EE   409600
#define EPG  1600
#define CH   128
#define NE   (EPG + NPG)   // edges per graph incl self-loops = 1800

// ---------------- scratch (device globals; no allocs allowed) ----------------
__device__ float g_h1[(size_t)NN * 512];
__device__ float g_h2[(size_t)NN * CH];
__device__ float g_o2[(size_t)NN * CH];
__device__ __nv_bfloat16 g_xh[(size_t)NN * 768];
__device__ __nv_bfloat16 g_xl[(size_t)NN * 768];
__device__ __nv_bfloat16 g_o1h[(size_t)NN * 512];
__device__ __nv_bfloat16 g_o1l[(size_t)NN * 512];
__device__ __nv_bfloat16 g_w1h[512 * 768];
__device__ __nv_bfloat16 g_w1l[512 * 768];
__device__ __nv_bfloat16 g_w2h[128 * 512];
__device__ __nv_bfloat16 g_w2l[128 * 512];
__device__ float g_S[NN * 2];
__device__ unsigned short g_csr[(size_t)GG * NE];
__device__ int g_csro[GG * (NPG + 1)];

#define SWZB(o) ((o) ^ (((o) >> 3) & 0x70))

// =============== fused prep: x split + W1/W2 split + CSR + loss init ===============
__global__ void prep(const float* __restrict__ x, __nv_bfloat16* __restrict__ xh,
                     __nv_bfloat16* __restrict__ xl,
                     const float* __restrict__ W1, const float* __restrict__ W2,
                     const int* __restrict__ es, const int* __restrict__ ed,
                     float* __restrict__ loss) {
    const int b = blockIdx.x, tid = threadIdx.x;
    if (b < 4096) {
        const size_t n4 = (size_t)NN * 768 / 4;
        size_t i = (size_t)b * 256 + tid;
        const size_t stride = 4096 * 256;
        for (; i < n4; i += stride) {
            float4 v = ((const float4*)x)[i];
            __nv_bfloat16 h0 = __float2bfloat16(v.x), h1 = __float2bfloat16(v.y);
            __nv_bfloat16 h2 = __float2bfloat16(v.z), h3 = __float2bfloat16(v.w);
            __nv_bfloat16 l0 = __float2bfloat16(v.x - __bfloat162float(h0));
            __nv_bfloat16 l1 = __float2bfloat16(v.y - __bfloat162float(h1));
            __nv_bfloat16 l2 = __float2bfloat16(v.z - __bfloat162float(h2));
            __nv_bfloat16 l3 = __float2bfloat16(v.w - __bfloat162float(h3));
            ((__nv_bfloat162*)xh)[2 * i]     = __halves2bfloat162(h0, h1);
            ((__nv_bfloat162*)xh)[2 * i + 1] = __halves2bfloat162(h2, h3);
            ((__nv_bfloat162*)xl)[2 * i]     = __halves2bfloat162(l0, l1);
            ((__nv_bfloat162*)xl)[2 * i + 1] = __halves2bfloat162(l2, l3);
        }
    } else if (b < 5888) {
        const bool w1 = (b < 5632);
        const int K = w1 ? 768 : 512, Nn = w1 ? 512 : 128;
        const float* W = w1 ? W1 : W2;
        __nv_bfloat16* hi = w1 ? g_w1h : g_w2h;
        __nv_bfloat16* lo = w1 ? g_w1l : g_w2l;
        int idx = (b - (w1 ? 4096 : 5632)) * 256 + tid;
        if (idx < Nn * K) {
            int n = idx / K, k = idx - n * K;
            float v = W[(size_t)k * Nn + n];
            __nv_bfloat16 h = __float2bfloat16(v);
            hi[idx] = h;
            lo[idx] = __float2bfloat16(v - __bfloat162float(h));
        }
    } else {
        const int g = b - 5888;
        if (g == 0 && tid == 0) *loss = 0.f;
        __shared__ int cnt[NPG + 1];
        __shared__ int cur[NPG];
        __shared__ unsigned short sd[NE];
        for (int i = tid; i <= NPG; i += blockDim.x) cnt[i] = 0;
        __syncthreads();
        for (int e = tid; e < NE; e += blockDim.x) {
            int d = (e < EPG) ? (ed[g * EPG + e] - g * NPG) : (e - EPG);
            sd[e] = (unsigned short)d;
            atomicAdd(&cnt[d], 1);
        }
        __syncthreads();
        if (tid == 0) {
            int run = 0;
            for (int i = 0; i < NPG; i++) {
                int c = cnt[i]; cnt[i] = run;
                g_csro[g * (NPG + 1) + i] = run;
                run += c;
            }
            g_csro[g * (NPG + 1) + NPG] = run;
        }
        __syncthreads();
        for (int i = tid; i < NPG; i += blockDim.x) cur[i] = cnt[i];
        __syncthreads();
        for (int e = tid; e < NE; e += blockDim.x) {
            int s = (e < EPG) ? (es[g * EPG + e] - g * NPG) : (e - EPG);
            int p = atomicAdd(&cur[sd[e]], 1);
            g_csr[(size_t)g * NE + p] = (unsigned short)s;
        }
    }
}

// ============================ HMMA split-bf16 GEMM (R16 config) ============================
__device__ __forceinline__ void ldsm4(uint32_t addr, uint32_t& r0, uint32_t& r1,
                                      uint32_t& r2, uint32_t& r3) {
    asm volatile("ldmatrix.sync.aligned.m8n8.x4.shared.b16 {%0,%1,%2,%3}, [%4];"
                 : "=r"(r0), "=r"(r1), "=r"(r2), "=r"(r3) : "r"(addr));
}

// C[M x Nn] = A[M x K] * B[Nn x K]^T via merged-pair iterations:
//   it < nk : stage {Ahi_k, Bhi_k, Blo_k}; compute Ahi*Bhi and Ahi*Blo from
//             ONE A-fragment load; it >= nk: stage {Alo_k, Bhi_k}.
// A ring = 2 x 16KB, B ring = 4 x 16KB (96KB -> 2 CTA/SM).
__global__ void __launch_bounds__(256, 2)
gemm_hmma(const __nv_bfloat16* __restrict__ Ahi, const __nv_bfloat16* __restrict__ Alo,
          const __nv_bfloat16* __restrict__ Bhi, const __nv_bfloat16* __restrict__ Blo,
          float* __restrict__ C, int Nn, int K) {
    constexpr int ATILE = 128 * 128;   // 16384 bytes per operand tile
    extern __shared__ char smb[];
    uint32_t sb;
    asm("{ .reg .u64 tt; cvta.to.shared.u64 tt, %1; cvt.u32.u64 %0, tt; }"
        : "=r"(sb) : "l"(smb));
    const int tid = threadIdx.x, lane = tid & 31, wid = tid >> 5;
    const int g = lane >> 2, t = lane & 3;
    const int bm = blockIdx.y * 128, bn = blockIdx.x * 128;
    const int wm = (wid >> 1) * 32, wn = (wid & 1) * 64;
    const int nk = K >> 6, nit = 2 * nk;
    const uint32_t bbase = sb + 2 * ATILE;
    const int aoff = ((lane & 7) + ((lane >> 3) & 1) * 8) * 128 + (lane >> 4) * 16;
    const int boff = ((lane & 7) + ((lane >> 4) & 1) * 8) * 128 + ((lane >> 3) & 1) * 16;

    float acc[2][8][4];
#pragma unroll
    for (int mf = 0; mf < 2; mf++)
#pragma unroll
        for (int nf = 0; nf < 8; nf++)
#pragma unroll
            for (int j = 0; j < 4; j++) acc[mf][nf][j] = 0.f;

    auto prefetch = [&](int it) {
        const bool merged = (it < nk);
        const int k = merged ? it : it - nk;
        const int kk = k << 6;
        const uint32_t ast  = sb + (it & 1) * ATILE;
        const uint32_t b1st = bbase + 2 * (it & 1) * ATILE;
        const __nv_bfloat16* Ag = (merged ? Ahi : Alo) + (size_t)bm * K + kk;
        const __nv_bfloat16* B1 = Bhi + (size_t)bn * K + kk;
#pragma unroll
        for (int u = 0; u < 4; u++) {
            int v = u * 256 + tid;
            int r = v >> 3, c16 = v & 7;
            asm volatile("cp.async.cg.shared.global [%0], [%1], 16;"
                         :: "r"(ast + SWZB(r * 128 + c16 * 16)),
                            "l"(Ag + (size_t)r * K + c16 * 8) : "memory");
        }
#pragma unroll
        for (int u = 0; u < 4; u++) {
            int v = u * 256 + tid;
            int r = v >> 3, c16 = v & 7;
            asm volatile("cp.async.cg.shared.global [%0], [%1], 16;"
                         :: "r"(b1st + SWZB(r * 128 + c16 * 16)),
                            "l"(B1 + (size_t)r * K + c16 * 8) : "memory");
        }
        if (merged) {
            const __nv_bfloat16* B2 = Blo + (size_t)bn * K + kk;
            const uint32_t b2st = b1st + ATILE;
#pragma unroll
            for (int u = 0; u < 4; u++) {
                int v = u * 256 + tid;
                int r = v >> 3, c16 = v & 7;
                asm volatile("cp.async.cg.shared.global [%0], [%1], 16;"
                             :: "r"(b2st + SWZB(r * 128 + c16 * 16)),
                                "l"(B2 + (size_t)r * K + c16 * 8) : "memory");
            }
        }
        asm volatile("cp.async.commit_group;" ::: "memory");
    };

    prefetch(0);
    prefetch(1);
    for (int it = 0; it < nit; it++) {
        if (it == nit - 1)
            asm volatile("cp.async.wait_group 0;" ::: "memory");
        else
            asm volatile("cp.async.wait_group 1;" ::: "memory");
        __syncthreads();
        const bool merged = (it < nk);
        const uint32_t ab = sb + (it & 1) * ATILE;
        const uint32_t bb = bbase + 2 * (it & 1) * ATILE;
#pragma unroll
        for (int ks = 0; ks < 4; ks++) {
            uint32_t af[2][4], bf[8][2];
#pragma unroll
            for (int mf = 0; mf < 2; mf++)
                ldsm4(ab + SWZB((wm + mf * 16) * 128 + ks * 32 + aoff),
                      af[mf][0], af[mf][1], af[mf][2], af[mf][3]);
#pragma unroll
            for (int nf2 = 0; nf2 < 4; nf2++)
                ldsm4(bb + SWZB((wn + nf2 * 16) * 128 + ks * 32 + boff),
                      bf[2 * nf2][0], bf[2 * nf2][1], bf[2 * nf2 + 1][0], bf[2 * nf2 + 1][1]);
#pragma unroll
            for (int mf = 0; mf < 2; mf++)
#pragma unroll
                for (int nf = 0; nf < 8; nf++) {
                    asm volatile(
                        "mma.sync.aligned.m16n8k16.row.col.f32.bf16.bf16.f32 "
                        "{%0,%1,%2,%3}, {%4,%5,%6,%7}, {%8,%9}, {%0,%1,%2,%3};"
                        : "+f"(acc[mf][nf][0]), "+f"(acc[mf][nf][1]),
                          "+f"(acc[mf][nf][2]), "+f"(acc[mf][nf][3])
                        : "r"(af[mf][0]), "r"(af[mf][1]), "r"(af[mf][2]), "r"(af[mf][3]),
                          "r"(bf[nf][0]), "r"(bf[nf][1]));
                }
            if (merged) {
#pragma unroll
                for (int nf2 = 0; nf2 < 4; nf2++)
                    ldsm4(bb + ATILE + SWZB((wn + nf2 * 16) * 128 + ks * 32 + boff),
                          bf[2 * nf2][0], bf[2 * nf2][1], bf[2 * nf2 + 1][0], bf[2 * nf2 + 1][1]);
#pragma unroll
                for (int mf = 0; mf < 2; mf++)
#pragma unroll
                    for (int nf = 0; nf < 8; nf++) {
                        asm volatile(
                            "mma.sync.aligned.m16n8k16.row.col.f32.bf16.bf16.f32 "
                            "{%0,%1,%2,%3}, {%4,%5,%6,%7}, {%8,%9}, {%0,%1,%2,%3};"
                            : "+f"(acc[mf][nf][0]), "+f"(acc[mf][nf][1]),
                              "+f"(acc[mf][nf][2]), "+f"(acc[mf][nf][3])
                            : "r"(af[mf][0]), "r"(af[mf][1]), "r"(af[mf][2]), "r"(af[mf][3]),
                              "r"(bf[nf][0]), "r"(bf[nf][1]));
                    }
            }
        }
        __syncthreads();
        if (it + 2 < nit) prefetch(it + 2);
    }

#pragma unroll
    for (int mf = 0; mf < 2; mf++)
#pragma unroll
        for (int nf = 0; nf < 8; nf++) {
            int row = bm + wm + mf * 16 + g;
            int col = bn + wn + nf * 8 + t * 2;
            *(float2*)&C[(size_t)row * Nn + col] =
                make_float2(acc[mf][nf][0], acc[mf][nf][1]);
            *(float2*)&C[(size_t)(row + 8) * Nn + col] =
                make_float2(acc[mf][nf][2], acc[mf][nf][3]);
        }
}

// ====== fused GAT: dots + softmax + aggregate (+optional cluster softmax) ======
// 512 threads (16 warps): smem-capacity-limited kernel, so 2x threads/SM for free.
__global__ void __launch_bounds__(512)
gat_agg(const float* __restrict__ h, const float* __restrict__ a_s,
        const float* __restrict__ a_d, const float* __restrict__ bias,
        float* __restrict__ outf, __nv_bfloat16* __restrict__ outh,
        __nv_bfloat16* __restrict__ outl,
        const float* __restrict__ Wc, const float* __restrict__ bc,
        float* __restrict__ S, int H, int stride) {
    extern __shared__ float smem[];
    float* hb  = smem;                       // NPG*CH
    float* asr = hb + NPG * CH;
    float* adr = asr + NPG;
    int* soff  = (int*)(adr + NPG);
    unsigned short* ssrc = (unsigned short*)(soff + NPG + 1);

    const int g = blockIdx.x, hd = blockIdx.y;
    const int tid = threadIdx.x, wid = tid >> 5, lane = tid & 31;
    const int nw = blockDim.x >> 5;
    const int base = g * NPG;

    for (int i = tid; i < NPG * (CH / 4); i += blockDim.x) {
        int r = i / (CH / 4), c4 = (i % (CH / 4)) * 4;
        *(float4*)&hb[r * CH + c4] =
            *(const float4*)(h + (size_t)(base + r) * stride + hd * CH + c4);
    }
    for (int i = tid; i <= NPG; i += blockDim.x) soff[i] = g_csro[g * (NPG + 1) + i];
    for (int i = tid; i < NE / 2; i += blockDim.x)
        ((uint32_t*)ssrc)[i] = ((const uint32_t*)(g_csr + (size_t)g * NE))[i];
    __syncthreads();

    {
        float4 s4 = *(const float4*)(a_s + hd * CH + lane * 4);
        float4 d4 = *(const float4*)(a_d + hd * CH + lane * 4);
        for (int r = wid; r < NPG; r += nw) {
            float4 v = *(float4*)&hb[r * CH + lane * 4];
            float ps = v.x * s4.x + v.y * s4.y + v.z * s4.z + v.w * s4.w;
            float pd = v.x * d4.x + v.y * d4.y + v.z * d4.z + v.w * d4.w;
#pragma unroll
            for (int o = 16; o; o >>= 1) {
                ps += __shfl_xor_sync(0xffffffffu, ps, o);
                pd += __shfl_xor_sync(0xffffffffu, pd, o);
            }
            if (lane == 0) { asr[r] = ps; adr[r] = pd; }
        }
    }
    __syncthreads();

    float2 w01[4];
    if (S) {
#pragma unroll
        for (int j = 0; j < 4; j++)
            w01[j] = *(const float2*)(Wc + (lane * 4 + j) * 2);
    }
    float bc0 = S ? bc[0] : 0.f, bc1 = S ? bc[1] : 0.f;

    for (int d = wid; d < NPG; d += nw) {
        const int j0 = soff[d], j1 = soff[d + 1];
        const float add = adr[d];
        float m = -1e30f;
        for (int j = j0; j < j1; j++) {
            float l = asr[ssrc[j]] + add;
            l = l > 0.f ? l : 0.2f * l;
            m = fmaxf(m, l);
        }
        float sum = 0.f;
        float4 acc = make_float4(0.f, 0.f, 0.f, 0.f);
        for (int j = j0; j < j1; j++) {
            int s = ssrc[j];
            float l = asr[s] + add;
            l = l > 0.f ? l : 0.2f * l;
            float e = expf(l - m);
            sum += e;
            float4 hv = *(float4*)&hb[s * CH + lane * 4];
            acc.x += e * hv.x; acc.y += e * hv.y;
            acc.z += e * hv.z; acc.w += e * hv.w;
        }
        float inv = 1.f / (sum + 1e-16f);
        float4 b4 = *(const float4*)(bias + hd * CH + lane * 4);
        acc.x = fmaxf(acc.x * inv + b4.x, 0.f);
        acc.y = fmaxf(acc.y * inv + b4.y, 0.f);
        acc.z = fmaxf(acc.z * inv + b4.z, 0.f);
        acc.w = fmaxf(acc.w * inv + b4.w, 0.f);
        size_t o = (size_t)(base + d) * stride + hd * CH + lane * 4;
        if (outf) *(float4*)(outf + o) = acc;
        if (outh) {
            __nv_bfloat16 h0 = __float2bfloat16(acc.x), h1 = __float2bfloat16(acc.y);
            __nv_bfloat16 h2 = __float2bfloat16(acc.z), h3 = __float2bfloat16(acc.w);
            *(__nv_bfloat162*)(outh + o)     = __halves2bfloat162(h0, h1);
            *(__nv_bfloat162*)(outh + o + 2) = __halves2bfloat162(h2, h3);
            __nv_bfloat16 l0 = __float2bfloat16(acc.x - __bfloat162float(h0));
            __nv_bfloat16 l1 = __float2bfloat16(acc.y - __bfloat162float(h1));
            __nv_bfloat16 l2 = __float2bfloat16(acc.z - __bfloat162float(h2));
            __nv_bfloat16 l3 = __float2bfloat16(acc.w - __bfloat162float(h3));
            *(__nv_bfloat162*)(outl + o)     = __halves2bfloat162(l0, l1);
            *(__nv_bfloat162*)(outl + o + 2) = __halves2bfloat162(l2, l3);
        }
        if (S) {
            float p0 = acc.x * w01[0].x + acc.y * w01[1].x + acc.z * w01[2].x + acc.w * w01[3].x;
            float p1 = acc.x * w01[0].y + acc.y * w01[1].y + acc.z * w01[2].y + acc.w * w01[3].y;
#pragma unroll
            for (int o2_ = 16; o2_; o2_ >>= 1) {
                p0 += __shfl_xor_sync(0xffffffffu, p0, o2_);
                p1 += __shfl_xor_sync(0xffffffffu, p1, o2_);
            }
            if (lane == 0) {
                float z0 = p0 + bc0, z1 = p1 + bc1;
                float mm = fmaxf(z0, z1);
                float e0 = expf(z0 - mm), e1 = expf(z1 - mm);
                float is = 1.f / (e0 + e1);
                S[(base + d) * 2] = e0 * is;
                S[(base + d) * 2 + 1] = e1 * is;
            }
        }
    }
}

// ============== merged head: aggregate loss + per-graph readout MLP ==============
__global__ void head_k(const float* __restrict__ S, const int* __restrict__ es,
                       const int* __restrict__ ed, const float* __restrict__ h2,
                       const float* __restrict__ Wf1, const float* __restrict__ bf1,
                       const float* __restrict__ Wf2, const float* __restrict__ bf2,
                       float* __restrict__ out, float* __restrict__ loss) {
    const int g = blockIdx.x, tid = threadIdx.x;   // 256 threads
    __shared__ float s0[NPG];
    __shared__ float sub[CH];
    __shared__ float hid[CH];
    __shared__ float sa[4];

    float a00 = 0.f, a01 = 0.f, a10 = 0.f, a11 = 0.f;
    for (int e = tid; e < EPG; e += blockDim.x) {
        int so = es[g * EPG + e], dn = ed[g * EPG + e];
        float ss0 = S[so * 2], ss1 = S[so * 2 + 1];
        float d0 = S[dn * 2], d1 = S[dn * 2 + 1];
        a00 += ss0 * d0; a01 += ss0 * d1; a10 += ss1 * d0; a11 += ss1 * d1;
    }
#pragma unroll
    for (int o = 16; o; o >>= 1) {
        a00 += __shfl_xor_sync(0xffffffffu, a00, o);
        a01 += __shfl_xor_sync(0xffffffffu, a01, o);
        a10 += __shfl_xor_sync(0xffffffffu, a10, o);
        a11 += __shfl_xor_sync(0xffffffffu, a11, o);
    }
    if (tid < 4) sa[tid] = 0.f;
    for (int i = tid; i < NPG; i += blockDim.x) s0[i] = S[(g * NPG + i) * 2];
    __syncthreads();
    if ((tid & 31) == 0) {
        atomicAdd(&sa[0], a00); atomicAdd(&sa[1], a01);
        atomicAdd(&sa[2], a10); atomicAdd(&sa[3], a11);
    }
    __syncthreads();
    if (tid == 0) {
        float r0 = fmaxf(fabsf(sa[0]) + fabsf(sa[1]), 1e-5f);
        float r1 = fmaxf(fabsf(sa[2]) + fabsf(sa[3]), 1e-5f);
        float d0 = sa[0] / r0 - 1.f, d1 = sa[3] / r1 - 1.f;
        float lg = 0.5f * (d0 * d0 + d1 * d1);
        atomicAdd(loss, lg * (1.f / (float)GG));
    }

    if (tid < CH) {
        float acc = 0.f;
        for (int n = 0; n < NPG; n++)
            acc += s0[n] * h2[(size_t)(g * NPG + n) * CH + tid];
        sub[tid] = acc;
    }
    __syncthreads();
    if (tid < CH) {
        float hh = bf1[tid];
        for (int c = 0; c < CH; c++) hh += sub[c] * Wf1[c * CH + tid];
        hid[tid] = fmaxf(hh, 0.f);
    }
    __syncthreads();
    int w = tid >> 5, lane = tid & 31;
    if (w < 2) {
        float p = 0.f;
        for (int j = lane; j < CH; j += 32) p += hid[j] * Wf2[j * 2 + w];
#pragma unroll
        for (int o = 16; o; o >>= 1) p += __shfl_down_sync(0xffffffffu, p, o);
        if (lane == 0) out[g * 2 + w] = p + bf2[w];
    }
}

// ============================ launcher ============================
extern "C" void kernel_launch(void* const* d_in, const int* in_sizes, int n_in,
                              void* d_out, int out_size) {
    const float* x   = (const float*)d_in[0];
    const int*   ei  = (const int*)d_in[1];
    const float* W1  = (const float*)d_in[3];
    const float* as1 = (const float*)d_in[4];
    const float* ad1 = (const float*)d_in[5];
    const float* b1  = (const float*)d_in[6];
    const float* W2  = (const float*)d_in[7];
    const float* as2 = (const float*)d_in[8];
    const float* ad2 = (const float*)d_in[9];
    const float* b2  = (const float*)d_in[10];
    const float* Wc  = (const float*)d_in[11];
    const float* bc  = (const float*)d_in[12];
    const float* Wf1 = (const float*)d_in[13];
    const float* bf1 = (const float*)d_in[14];
    const float* Wf2 = (const float*)d_in[15];
    const float* bf2 = (const float*)d_in[16];
    const int* es = ei;
    const int* ed = ei + EE;
    float* out = (float*)d_out;

    float *h1, *h2, *o2, *S;
    __nv_bfloat16 *xh, *xl, *o1h, *o1l, *w1h, *w1l, *w2h, *w2l;
    cudaGetSymbolAddress((void**)&h1, g_h1);
    cudaGetSymbolAddress((void**)&h2, g_h2);
    cudaGetSymbolAddress((void**)&o2, g_o2);
    cudaGetSymbolAddress((void**)&xh, g_xh);
    cudaGetSymbolAddress((void**)&xl, g_xl);
    cudaGetSymbolAddress((void**)&o1h, g_o1h);
    cudaGetSymbolAddress((void**)&o1l, g_o1l);
    cudaGetSymbolAddress((void**)&w1h, g_w1h);
    cudaGetSymbolAddress((void**)&w1l, g_w1l);
    cudaGetSymbolAddress((void**)&w2h, g_w2h);
    cudaGetSymbolAddress((void**)&w2l, g_w2l);
    cudaGetSymbolAddress((void**)&S, g_S);

    const int GAT_SMEM = NPG * CH * 4 + 2 * NPG * 4 + (NPG + 1) * 4 + NE * 2;
    const int GEMM_SMEM = 6 * 128 * 128;   // 2 A bufs + 4 B bufs = 98304
    cudaFuncSetAttribute(gat_agg, cudaFuncAttributeMaxDynamicSharedMemorySize, GAT_SMEM);
    cudaFuncSetAttribute(gemm_hmma, cudaFuncAttributeMaxDynamicSharedMemorySize, GEMM_SMEM);

    // fused prep (x split + W splits + CSR + loss zero)
    prep<<<6144, 256>>>(x, xh, xl, W1, W2, es, ed, out + (out_size - 1));

    // layer 1: [NN,768] x [768,512]
    gemm_hmma<<<dim3(4, 400), 256, GEMM_SMEM>>>(xh, xl, w1h, w1l, h1, 512, 768);
    gat_agg<<<dim3(GG, 4), 512, GAT_SMEM>>>(h1, as1, ad1, b1,
                                            nullptr, o1h, o1l,
                                            nullptr, nullptr, nullptr, 4, 512);
    // layer 2: [NN,512] x [512,128]
    gemm_hmma<<<dim3(1, 400), 256, GEMM_SMEM>>>(o1h, o1l, w2h, w2l, h2, 128, 512);
    gat_agg<<<dim3(GG, 1), 512, GAT_SMEM>>>(h2, as2, ad2, b2,
                                            o2, nullptr, nullptr,
                                            Wc, bc, S, 1, 128);
    // merged head
    head_k<<<GG, 256>>>(S, es, ed, o2, Wf1, bf1, Wf2, bf2, out, out + (out_size - 1));
}